// round 9
// baseline (speedup 1.0000x reference)
#include <cuda_runtime.h>
#include <cuda_bf16.h>
#include <cstdint>

#define BB   16
#define NN   16384
#define GS   16
#define GG   1024
#define HID  768
#define ED   384

// output layout (floats): tokens | centers | group_idx(as float)
#define TOK_OFF 0
#define CEN_OFF (BB*GG*ED)
#define IDX_OFF (CEN_OFF + BB*GG*3)
#define TOT_SZ  (IDX_OFF + BB*GG*GS)

// GEMM tiling
#define NPT 128                  // points per CTA (8 groups)
#define KCH 64                   // K chunk
#define NKC (HID/KCH)            // 12
#define TILE_B 16384             // one 128x64 bf16 tile

// smem layout (bytes)
#define SM_W2(bi) ((bi)*32768)            // hi +0, lo +16384
#define SM_H(bi)  (65536 + (bi)*32768)    // hi +0, lo +16384
#define SM_REL    131072                  // 384 floats
#define SM_CEN    132608                  // 24 floats
#define SM_TOTAL  132736

__device__ float g_mm[BB * 6];
__device__ int   g_sidx[BB * NN];
__device__ __align__(16) char g_w2hi[3 * NKC * TILE_B];
__device__ __align__(16) char g_w2lo[3 * NKC * TILE_B];

__device__ __forceinline__ float gelu_exact(float x) {
    return 0.5f * x * (1.0f + erff(x * 0.70710678118654752f));
}
__device__ __forceinline__ int part1by2_10(int v) {
    v &= 1023;
    v = (v | (v << 16)) & 50331903;
    v = (v | (v << 8))  & 50393103;
    v = (v | (v << 4))  & 51130563;
    v = (v | (v << 2))  & 153391689;
    return v;
}
__device__ __forceinline__ uint32_t smem_u32(const void* p) {
    uint32_t a;
    asm("{ .reg .u64 t; cvta.to.shared.u64 t, %1; cvt.u32.u64 %0, t; }" : "=r"(a) : "l"(p));
    return a;
}
__device__ __forceinline__ void ldmx4(uint32_t* r, uint32_t a) {
    asm volatile("ldmatrix.sync.aligned.m8n8.x4.shared.b16 {%0,%1,%2,%3}, [%4];"
        : "=r"(r[0]), "=r"(r[1]), "=r"(r[2]), "=r"(r[3]) : "r"(a));
}
__device__ __forceinline__ void mma16816(float* c, const uint32_t* a, const uint32_t* b) {
    asm volatile(
        "mma.sync.aligned.m16n8k16.row.col.f32.bf16.bf16.f32 "
        "{%0,%1,%2,%3}, {%4,%5,%6,%7}, {%8,%9}, {%0,%1,%2,%3};"
        : "+f"(c[0]), "+f"(c[1]), "+f"(c[2]), "+f"(c[3])
        : "r"(a[0]), "r"(a[1]), "r"(a[2]), "r"(a[3]), "r"(b[0]), "r"(b[1]));
}
__device__ __forceinline__ uint32_t pack_bf2(__nv_bfloat16 a, __nv_bfloat16 b) {
    return (uint32_t)__bfloat16_as_ushort(a) | ((uint32_t)__bfloat16_as_ushort(b) << 16);
}

// ---------------- Kernel A: per-batch min/max (FROZEN) ----------------
__global__ void k_minmax(const float* __restrict__ xyz) {
    int b = blockIdx.x;
    int t = threadIdx.x;
    const float* p = xyz + (size_t)b * NN * 3;
    float mn0 = 1e30f, mn1 = 1e30f, mn2 = 1e30f;
    float mx0 = -1e30f, mx1 = -1e30f, mx2 = -1e30f;
    for (int i = t; i < NN; i += blockDim.x) {
        float v0 = p[i * 3], v1 = p[i * 3 + 1], v2 = p[i * 3 + 2];
        mn0 = fminf(mn0, v0); mx0 = fmaxf(mx0, v0);
        mn1 = fminf(mn1, v1); mx1 = fmaxf(mx1, v1);
        mn2 = fminf(mn2, v2); mx2 = fmaxf(mx2, v2);
    }
    __shared__ float s[6][256];
    s[0][t] = mn0; s[1][t] = mn1; s[2][t] = mn2;
    s[3][t] = mx0; s[4][t] = mx1; s[5][t] = mx2;
    __syncthreads();
    for (int w = 128; w > 0; w >>= 1) {
        if (t < w) {
            #pragma unroll
            for (int c = 0; c < 3; c++) {
                s[c][t]     = fminf(s[c][t],     s[c][t + w]);
                s[c + 3][t] = fmaxf(s[c + 3][t], s[c + 3][t + w]);
            }
        }
        __syncthreads();
    }
    if (t < 6) g_mm[b * 6 + t] = s[t][0];
}

// ---------------- Kernel B: morton + stable bitonic argsort (FROZEN) ----------------
__global__ void k_sort(const float* __restrict__ xyz, float* __restrict__ out, int out_size) {
    extern __shared__ unsigned long long keys[];
    int b = blockIdx.x;
    int t = threadIdx.x;
    float mn0 = g_mm[b * 6 + 0], mn1 = g_mm[b * 6 + 1], mn2 = g_mm[b * 6 + 2];
    float s0 = fmaxf(__fsub_rn(g_mm[b * 6 + 3], mn0), 1e-6f);
    float s1 = fmaxf(__fsub_rn(g_mm[b * 6 + 4], mn1), 1e-6f);
    float s2 = fmaxf(__fsub_rn(g_mm[b * 6 + 5], mn2), 1e-6f);
    float r0 = __fdiv_rn(1.0f, s0);
    float r1 = __fdiv_rn(1.0f, s1);
    float r2 = __fdiv_rn(1.0f, s2);
    const float* p = xyz + (size_t)b * NN * 3;

    for (int i = t; i < NN; i += blockDim.x) {
        float u0 = __fmul_rn(__fsub_rn(p[i * 3],     mn0), r0);
        float u1 = __fmul_rn(__fsub_rn(p[i * 3 + 1], mn1), r1);
        float u2 = __fmul_rn(__fsub_rn(p[i * 3 + 2], mn2), r2);
        int q0 = min(max(__float2int_rn(__fmul_rn(u0, 1023.0f)), 0), 1023);
        int q1 = min(max(__float2int_rn(__fmul_rn(u1, 1023.0f)), 0), 1023);
        int q2 = min(max(__float2int_rn(__fmul_rn(u2, 1023.0f)), 0), 1023);
        int code = part1by2_10(q0) | (part1by2_10(q1) << 1) | (part1by2_10(q2) << 2);
        keys[i] = ((unsigned long long)(unsigned)code << 14) | (unsigned long long)i;
    }
    __syncthreads();

    for (int k = 2; k <= NN; k <<= 1) {
        for (int j = k >> 1; j > 0; j >>= 1) {
            for (int i = t; i < NN; i += blockDim.x) {
                int ixj = i ^ j;
                if (ixj > i) {
                    unsigned long long a = keys[i], c = keys[ixj];
                    bool up = ((i & k) == 0);
                    if ((a > c) == up) { keys[i] = c; keys[ixj] = a; }
                }
            }
            __syncthreads();
        }
    }

    for (int i = t; i < NN; i += blockDim.x) {
        int si = (int)(keys[i] & 16383ULL);
        g_sidx[b * NN + i] = si;
        if (out_size >= TOT_SZ) out[IDX_OFF + b * NN + i] = (float)si;
    }
}

// ---------------- Kernel P: W2 -> bf16 hi/lo transposed + swizzled tiles ----------------
__global__ void k_prep(const float* __restrict__ W2) {
    int idx = blockIdx.x * 256 + threadIdx.x;
    if (idx >= HID * ED) return;
    int k = idx / ED, n = idx - k * ED;
    float w = W2[idx];
    __nv_bfloat16 hi = __float2bfloat16(w);
    __nv_bfloat16 lo = __float2bfloat16(w - __bfloat162float(hi));
    int mc = n >> 7, row = n & 127, kc = k >> 6, col = k & 63;
    uint32_t off = (uint32_t)(row * 128 + col * 2);
    off ^= (off >> 3) & 0x70;
    size_t tile = (size_t)(mc * NKC + kc) * TILE_B;
    *(__nv_bfloat16*)(g_w2hi + tile + off) = hi;
    *(__nv_bfloat16*)(g_w2lo + tile + off) = lo;
}

// ---------------- Kernel C: fused gather + MLP via mma.sync split-bf16 ----------------
__global__ void __launch_bounds__(256, 1) k_gemm(
    const float* __restrict__ xyz,
    const float* __restrict__ W1, const float* __restrict__ b1,
    const float* __restrict__ b2,
    const float* __restrict__ Wc, const float* __restrict__ bc,
    float* __restrict__ out, int out_size)
{
    extern __shared__ char sm[];
    uint32_t smb = smem_u32(sm);
    float* rel = (float*)(sm + SM_REL);
    float* cen = (float*)(sm + SM_CEN);

    int t = threadIdx.x, wid = t >> 5, lane = t & 31;
    int blk = blockIdx.x;                 // 2048
    int b = blk >> 7;
    int chunk = blk & 127;
    int gbase = chunk * 8;
    int m0 = chunk * NPT;

    // gather sorted points
    if (t < NPT) {
        int si = g_sidx[b * NN + m0 + t];
        const float* pp = xyz + ((size_t)b * NN + si) * 3;
        rel[t * 3 + 0] = pp[0];
        rel[t * 3 + 1] = pp[1];
        rel[t * 3 + 2] = pp[2];
    }
    __syncthreads();
    if (t < 24) {
        int g = t / 3, cc = t - g * 3;
        float sum = 0.f;
        #pragma unroll
        for (int p = 0; p < GS; p++) sum += rel[(g * GS + p) * 3 + cc];
        float cv = sum * (1.0f / GS);
        cen[t] = cv;
        if (out_size >= CEN_OFF + BB * GG * 3)
            out[CEN_OFF + ((size_t)b * GG + gbase + g) * 3 + cc] = cv;
    }
    __syncthreads();
    for (int i = t; i < NPT * 3; i += 256) rel[i] -= cen[(i / (GS * 3)) * 3 + i % 3];
    __syncthreads();

    int p = t & 127;
    float rx = rel[p * 3], ry = rel[p * 3 + 1], rz = rel[p * 3 + 2];
    int kh = t >> 7;                      // which 32-k half this thread fills
    uint32_t hswz = (uint32_t)((p & 7) << 4);
    uint32_t hrow = (uint32_t)(p * 128);

    // layer-1 + gelu + split for K-chunk kc into H buffer hb (vectorized STS.128)
    auto computeH = [&](int kc, int hb) {
        char* hbp = sm + SM_H(hb);
        #pragma unroll
        for (int i = 0; i < 4; i++) {
            int k  = kh * 32 + i * 8;
            int kk = kc * KCH + k;
            float4 wa0 = *(const float4*)(W1 + kk);
            float4 wa1 = *(const float4*)(W1 + kk + 4);
            float4 wb0 = *(const float4*)(W1 + HID + kk);
            float4 wb1 = *(const float4*)(W1 + HID + kk + 4);
            float4 wc0 = *(const float4*)(W1 + 2 * HID + kk);
            float4 wc1 = *(const float4*)(W1 + 2 * HID + kk + 4);
            float4 bb0 = *(const float4*)(b1 + kk);
            float4 bb1 = *(const float4*)(b1 + kk + 4);
            float h[8];
            h[0] = gelu_exact(fmaf(rx, wa0.x, fmaf(ry, wb0.x, fmaf(rz, wc0.x, bb0.x))));
            h[1] = gelu_exact(fmaf(rx, wa0.y, fmaf(ry, wb0.y, fmaf(rz, wc0.y, bb0.y))));
            h[2] = gelu_exact(fmaf(rx, wa0.z, fmaf(ry, wb0.z, fmaf(rz, wc0.z, bb0.z))));
            h[3] = gelu_exact(fmaf(rx, wa0.w, fmaf(ry, wb0.w, fmaf(rz, wc0.w, bb0.w))));
            h[4] = gelu_exact(fmaf(rx, wa1.x, fmaf(ry, wb1.x, fmaf(rz, wc1.x, bb1.x))));
            h[5] = gelu_exact(fmaf(rx, wa1.y, fmaf(ry, wb1.y, fmaf(rz, wc1.y, bb1.y))));
            h[6] = gelu_exact(fmaf(rx, wa1.z, fmaf(ry, wb1.z, fmaf(rz, wc1.z, bb1.z))));
            h[7] = gelu_exact(fmaf(rx, wa1.w, fmaf(ry, wb1.w, fmaf(rz, wc1.w, bb1.w))));
            uint32_t hw[4], lw[4];
            #pragma unroll
            for (int j = 0; j < 4; j++) {
                __nv_bfloat16 e0 = __float2bfloat16(h[2 * j]);
                __nv_bfloat16 e1 = __float2bfloat16(h[2 * j + 1]);
                hw[j] = pack_bf2(e0, e1);
                __nv_bfloat16 l0 = __float2bfloat16(h[2 * j]     - __bfloat162float(e0));
                __nv_bfloat16 l1 = __float2bfloat16(h[2 * j + 1] - __bfloat162float(e1));
                lw[j] = pack_bf2(l0, l1);
            }
            uint32_t off = hrow + (((uint32_t)(k * 2)) ^ hswz);
            *(uint4*)(hbp + off)         = make_uint4(hw[0], hw[1], hw[2], hw[3]);
            *(uint4*)(hbp + 16384 + off) = make_uint4(lw[0], lw[1], lw[2], lw[3]);
        }
    };

    // cp.async stage of one pre-swizzled W2 tile pair into buffer bi
    auto cp_issue = [&](int mc, int kc, int bi) {
        size_t tile = (size_t)(mc * NKC + kc) * TILE_B;
        const char* sh = g_w2hi + tile;
        const char* sl = g_w2lo + tile;
        uint32_t dh = smb + SM_W2(bi);
        #pragma unroll
        for (int i = 0; i < 4; i++) {
            uint32_t o = (uint32_t)(t * 16 + i * 4096);
            asm volatile("cp.async.cg.shared.global [%0], [%1], 16;"
                :: "r"(dh + o), "l"(__cvta_generic_to_global(sh + o)) : "memory");
            asm volatile("cp.async.cg.shared.global [%0], [%1], 16;"
                :: "r"(dh + 16384 + o), "l"(__cvta_generic_to_global(sl + o)) : "memory");
        }
        asm volatile("cp.async.commit_group;" ::: "memory");
    };

    int m0w = (wid & 3) * 32;      // warp M offset (embed cols within 128)
    int n0w = (wid >> 2) * 64;     // warp N offset (points)

    // precompute all ldmatrix byte offsets (loop-invariant; one IADD per use)
    uint32_t offA[2][4], offB[4][4];
    {
        int la = lane & 15, sa = (lane >> 4) << 4;
        #pragma unroll
        for (int mf = 0; mf < 2; mf++) {
            int row = m0w + mf * 16 + la;
            uint32_t swz = (uint32_t)((row & 7) << 4);
            #pragma unroll
            for (int ks = 0; ks < 4; ks++)
                offA[mf][ks] = (uint32_t)(row * 128) + (((uint32_t)(ks * 32 + sa)) ^ swz);
        }
        int g = lane >> 3, nfs = g >> 1, khl = (g & 1) << 4, lb = lane & 7;
        #pragma unroll
        for (int nfp = 0; nfp < 4; nfp++) {
            int row = n0w + (nfp * 2 + nfs) * 8 + lb;
            uint32_t swz = (uint32_t)((row & 7) << 4);
            #pragma unroll
            for (int ks = 0; ks < 4; ks++)
                offB[nfp][ks] = (uint32_t)(row * 128) + (((uint32_t)(ks * 32 + khl)) ^ swz);
        }
    }

    for (int mc = 0; mc < 3; mc++) {
        float c[2][8][4];
        #pragma unroll
        for (int mf = 0; mf < 2; mf++)
            #pragma unroll
            for (int nf = 0; nf < 8; nf++)
                #pragma unroll
                for (int q = 0; q < 4; q++) c[mf][nf][q] = 0.f;

        cp_issue(mc, 0, 0);
        cp_issue(mc, 1, 1);
        computeH(0, 0);

        for (int kc = 0; kc < NKC; kc++) {
            int bi = kc & 1;
            if (kc < NKC - 1) { asm volatile("cp.async.wait_group 1;" ::: "memory"); }
            else              { asm volatile("cp.async.wait_group 0;" ::: "memory"); }
            __syncthreads();

            uint32_t wbase = smb + SM_W2(bi);
            uint32_t hbase = smb + SM_H(bi);
            #pragma unroll
            for (int ks = 0; ks < 4; ks++) {
                uint32_t ahi[2][4], alo[2][4];
                #pragma unroll
                for (int mf = 0; mf < 2; mf++) {
                    ldmx4(ahi[mf], wbase + offA[mf][ks]);
                    ldmx4(alo[mf], wbase + 16384 + offA[mf][ks]);
                }
                #pragma unroll
                for (int nfp = 0; nfp < 4; nfp++) {
                    uint32_t bh[4], bl[4];
                    ldmx4(bh, hbase + offB[nfp][ks]);
                    ldmx4(bl, hbase + 16384 + offB[nfp][ks]);
                    #pragma unroll
                    for (int half = 0; half < 2; half++) {
                        int nf = nfp * 2 + half;
                        #pragma unroll
                        for (int mf = 0; mf < 2; mf++) {
                            mma16816(c[mf][nf], ahi[mf], bh + 2 * half);
                            mma16816(c[mf][nf], ahi[mf], bl + 2 * half);
                            mma16816(c[mf][nf], alo[mf], bh + 2 * half);
                        }
                    }
                }
            }
            __syncthreads();

            if (kc + 2 < NKC) cp_issue(mc, kc + 2, bi);
            if (kc + 1 < NKC) computeH(kc + 1, (kc + 1) & 1);
        }

        // epilogue: bias + gelu + group max (quad shuffle) + center proj
        #pragma unroll
        for (int mf = 0; mf < 2; mf++) {
            int row0 = mc * 128 + m0w + mf * 16 + (lane >> 2);
            int row1 = row0 + 8;
            float bias0 = b2[row0], bias1 = b2[row1];
            #pragma unroll
            for (int g = 0; g < 4; g++) {
                float va = -1e30f, vb = -1e30f;
                #pragma unroll
                for (int q = 0; q < 2; q++) {
                    float* cc = c[mf][2 * g + q];
                    va = fmaxf(va, fmaxf(gelu_exact(cc[0] + bias0), gelu_exact(cc[1] + bias0)));
                    vb = fmaxf(vb, fmaxf(gelu_exact(cc[2] + bias1), gelu_exact(cc[3] + bias1)));
                }
                va = fmaxf(va, __shfl_xor_sync(0xffffffffu, va, 1));
                va = fmaxf(va, __shfl_xor_sync(0xffffffffu, va, 2));
                vb = fmaxf(vb, __shfl_xor_sync(0xffffffffu, vb, 1));
                vb = fmaxf(vb, __shfl_xor_sync(0xffffffffu, vb, 2));
                if ((lane & 3) == 0) {
                    int gl = (wid >> 2) * 4 + g;
                    int gg = gbase + gl;
                    float c0_ = cen[gl * 3], c1_ = cen[gl * 3 + 1], c2_ = cen[gl * 3 + 2];
                    out[TOK_OFF + ((size_t)b * GG + gg) * ED + row0] =
                        va + c0_ * Wc[row0] + c1_ * Wc[ED + row0] + c2_ * Wc[2 * ED + row0] + bc[row0];
                    out[TOK_OFF + ((size_t)b * GG + gg) * ED + row1] =
                        vb + c0_ * Wc[row1] + c1_ * Wc[ED + row1] + c2_ * Wc[2 * ED + row1] + bc[row1];
                }
            }
        }
        __syncthreads();
    }
}

extern "C" void kernel_launch(void* const* d_in, const int* in_sizes, int n_in,
                              void* d_out, int out_size) {
    const float* xyz = (const float*)d_in[0];
    const float* W1  = (const float*)d_in[1];
    const float* b1  = (const float*)d_in[2];
    const float* W2  = (const float*)d_in[3];
    const float* b2  = (const float*)d_in[4];
    const float* Wc  = (const float*)d_in[5];
    const float* bc  = (const float*)d_in[6];
    float* out = (float*)d_out;

    const int sort_smem = NN * 8;
    cudaFuncSetAttribute(k_sort, cudaFuncAttributeMaxDynamicSharedMemorySize, sort_smem);
    cudaFuncSetAttribute(k_gemm, cudaFuncAttributeMaxDynamicSharedMemorySize, SM_TOTAL);

    k_minmax<<<BB, 256>>>(xyz);
    k_sort<<<BB, 1024, sort_smem>>>(xyz, out, out_size);
    k_prep<<<(HID * ED + 255) / 256, 256>>>(W2);
    k_gemm<<<BB * NN / NPT, 256, SM_TOTAL>>>(xyz, W1, b1, b2, Wc, bc, out, out_size);
}

// round 10
// speedup vs baseline: 1.4111x; 1.4111x over previous
#include <cuda_runtime.h>
#include <cuda_bf16.h>
#include <cstdint>

#define BB   16
#define NN   16384
#define GS   16
#define GG   1024
#define HID  768
#define ED   384

// output layout (floats): tokens | centers | group_idx(as float)
#define TOK_OFF 0
#define CEN_OFF (BB*GG*ED)
#define IDX_OFF (CEN_OFF + BB*GG*3)
#define TOT_SZ  (IDX_OFF + BB*GG*GS)

// GEMM tiling
#define NPT 128                  // points per CTA (8 groups)
#define KCH 64                   // K chunk
#define NKC (HID/KCH)            // 12
#define TILE_B 16384             // one 128x64 bf16 tile
#define NTH 512                  // threads per CTA (16 warps)

// smem layout (bytes)
#define SM_W2(bi) ((bi)*32768)            // hi +0, lo +16384
#define SM_H(bi)  (65536 + (bi)*32768)    // hi +0, lo +16384
#define SM_REL    131072                  // 384 floats
#define SM_CEN    132608                  // 24 floats
#define SM_TOTAL  132736

__device__ float g_mm[BB * 6];
__device__ int   g_sidx[BB * NN];
__device__ __align__(16) char g_w2hi[3 * NKC * TILE_B];
__device__ __align__(16) char g_w2lo[3 * NKC * TILE_B];

__device__ __forceinline__ float gelu_exact(float x) {
    return 0.5f * x * (1.0f + erff(x * 0.70710678118654752f));
}
__device__ __forceinline__ int part1by2_10(int v) {
    v &= 1023;
    v = (v | (v << 16)) & 50331903;
    v = (v | (v << 8))  & 50393103;
    v = (v | (v << 4))  & 51130563;
    v = (v | (v << 2))  & 153391689;
    return v;
}
__device__ __forceinline__ uint32_t smem_u32(const void* p) {
    uint32_t a;
    asm("{ .reg .u64 t; cvta.to.shared.u64 t, %1; cvt.u32.u64 %0, t; }" : "=r"(a) : "l"(p));
    return a;
}
__device__ __forceinline__ void ldmx4(uint32_t* r, uint32_t a) {
    asm volatile("ldmatrix.sync.aligned.m8n8.x4.shared.b16 {%0,%1,%2,%3}, [%4];"
        : "=r"(r[0]), "=r"(r[1]), "=r"(r[2]), "=r"(r[3]) : "r"(a));
}
__device__ __forceinline__ void ldmx2(uint32_t* r, uint32_t a) {
    asm volatile("ldmatrix.sync.aligned.m8n8.x2.shared.b16 {%0,%1}, [%2];"
        : "=r"(r[0]), "=r"(r[1]) : "r"(a));
}
__device__ __forceinline__ void mma16816(float* c, const uint32_t* a, const uint32_t* b) {
    asm volatile(
        "mma.sync.aligned.m16n8k16.row.col.f32.bf16.bf16.f32 "
        "{%0,%1,%2,%3}, {%4,%5,%6,%7}, {%8,%9}, {%0,%1,%2,%3};"
        : "+f"(c[0]), "+f"(c[1]), "+f"(c[2]), "+f"(c[3])
        : "r"(a[0]), "r"(a[1]), "r"(a[2]), "r"(a[3]), "r"(b[0]), "r"(b[1]));
}

// ---------------- Kernel A: per-batch min/max (FROZEN) ----------------
__global__ void k_minmax(const float* __restrict__ xyz) {
    int b = blockIdx.x;
    int t = threadIdx.x;
    const float* p = xyz + (size_t)b * NN * 3;
    float mn0 = 1e30f, mn1 = 1e30f, mn2 = 1e30f;
    float mx0 = -1e30f, mx1 = -1e30f, mx2 = -1e30f;
    for (int i = t; i < NN; i += blockDim.x) {
        float v0 = p[i * 3], v1 = p[i * 3 + 1], v2 = p[i * 3 + 2];
        mn0 = fminf(mn0, v0); mx0 = fmaxf(mx0, v0);
        mn1 = fminf(mn1, v1); mx1 = fmaxf(mx1, v1);
        mn2 = fminf(mn2, v2); mx2 = fmaxf(mx2, v2);
    }
    __shared__ float s[6][256];
    s[0][t] = mn0; s[1][t] = mn1; s[2][t] = mn2;
    s[3][t] = mx0; s[4][t] = mx1; s[5][t] = mx2;
    __syncthreads();
    for (int w = 128; w > 0; w >>= 1) {
        if (t < w) {
            #pragma unroll
            for (int c = 0; c < 3; c++) {
                s[c][t]     = fminf(s[c][t],     s[c][t + w]);
                s[c + 3][t] = fmaxf(s[c + 3][t], s[c + 3][t + w]);
            }
        }
        __syncthreads();
    }
    if (t < 6) g_mm[b * 6 + t] = s[t][0];
}

// ---------------- Kernel B: morton + stable bitonic argsort (FROZEN) ----------------
__global__ void k_sort(const float* __restrict__ xyz, float* __restrict__ out, int out_size) {
    extern __shared__ unsigned long long keys[];
    int b = blockIdx.x;
    int t = threadIdx.x;
    float mn0 = g_mm[b * 6 + 0], mn1 = g_mm[b * 6 + 1], mn2 = g_mm[b * 6 + 2];
    float s0 = fmaxf(__fsub_rn(g_mm[b * 6 + 3], mn0), 1e-6f);
    float s1 = fmaxf(__fsub_rn(g_mm[b * 6 + 4], mn1), 1e-6f);
    float s2 = fmaxf(__fsub_rn(g_mm[b * 6 + 5], mn2), 1e-6f);
    float r0 = __fdiv_rn(1.0f, s0);
    float r1 = __fdiv_rn(1.0f, s1);
    float r2 = __fdiv_rn(1.0f, s2);
    const float* p = xyz + (size_t)b * NN * 3;

    for (int i = t; i < NN; i += blockDim.x) {
        float u0 = __fmul_rn(__fsub_rn(p[i * 3],     mn0), r0);
        float u1 = __fmul_rn(__fsub_rn(p[i * 3 + 1], mn1), r1);
        float u2 = __fmul_rn(__fsub_rn(p[i * 3 + 2], mn2), r2);
        int q0 = min(max(__float2int_rn(__fmul_rn(u0, 1023.0f)), 0), 1023);
        int q1 = min(max(__float2int_rn(__fmul_rn(u1, 1023.0f)), 0), 1023);
        int q2 = min(max(__float2int_rn(__fmul_rn(u2, 1023.0f)), 0), 1023);
        int code = part1by2_10(q0) | (part1by2_10(q1) << 1) | (part1by2_10(q2) << 2);
        keys[i] = ((unsigned long long)(unsigned)code << 14) | (unsigned long long)i;
    }
    __syncthreads();

    for (int k = 2; k <= NN; k <<= 1) {
        for (int j = k >> 1; j > 0; j >>= 1) {
            for (int i = t; i < NN; i += blockDim.x) {
                int ixj = i ^ j;
                if (ixj > i) {
                    unsigned long long a = keys[i], c = keys[ixj];
                    bool up = ((i & k) == 0);
                    if ((a > c) == up) { keys[i] = c; keys[ixj] = a; }
                }
            }
            __syncthreads();
        }
    }

    for (int i = t; i < NN; i += blockDim.x) {
        int si = (int)(keys[i] & 16383ULL);
        g_sidx[b * NN + i] = si;
        if (out_size >= TOT_SZ) out[IDX_OFF + b * NN + i] = (float)si;
    }
}

// ---------------- Kernel P: W2 -> bf16 hi/lo transposed + swizzled tiles ----------------
__global__ void k_prep(const float* __restrict__ W2) {
    int idx = blockIdx.x * 256 + threadIdx.x;
    if (idx >= HID * ED) return;
    int k = idx / ED, n = idx - k * ED;
    float w = W2[idx];
    __nv_bfloat16 hi = __float2bfloat16(w);
    __nv_bfloat16 lo = __float2bfloat16(w - __bfloat162float(hi));
    int mc = n >> 7, row = n & 127, kc = k >> 6, col = k & 63;
    uint32_t off = (uint32_t)(row * 128 + col * 2);
    off ^= (off >> 3) & 0x70;
    size_t tile = (size_t)(mc * NKC + kc) * TILE_B;
    *(__nv_bfloat16*)(g_w2hi + tile + off) = hi;
    *(__nv_bfloat16*)(g_w2lo + tile + off) = lo;
}

// ---------------- Kernel C: fused gather + MLP via mma.sync split-bf16, 16 warps ----------------
__global__ void __launch_bounds__(NTH, 1) k_gemm(
    const float* __restrict__ xyz,
    const float* __restrict__ W1, const float* __restrict__ b1,
    const float* __restrict__ b2,
    const float* __restrict__ Wc, const float* __restrict__ bc,
    float* __restrict__ out, int out_size)
{
    extern __shared__ char sm[];
    uint32_t smb = smem_u32(sm);
    float* rel = (float*)(sm + SM_REL);
    float* cen = (float*)(sm + SM_CEN);

    int t = threadIdx.x, wid = t >> 5, lane = t & 31;
    int blk = blockIdx.x;                 // 2048
    int b = blk >> 7;
    int chunk = blk & 127;
    int gbase = chunk * 8;
    int m0 = chunk * NPT;

    // gather sorted points
    if (t < NPT) {
        int si = g_sidx[b * NN + m0 + t];
        const float* pp = xyz + ((size_t)b * NN + si) * 3;
        rel[t * 3 + 0] = pp[0];
        rel[t * 3 + 1] = pp[1];
        rel[t * 3 + 2] = pp[2];
    }
    __syncthreads();
    if (t < 24) {
        int g = t / 3, cc = t - g * 3;
        float sum = 0.f;
        #pragma unroll
        for (int p = 0; p < GS; p++) sum += rel[(g * GS + p) * 3 + cc];
        float cv = sum * (1.0f / GS);
        cen[t] = cv;
        if (out_size >= CEN_OFF + BB * GG * 3)
            out[CEN_OFF + ((size_t)b * GG + gbase + g) * 3 + cc] = cv;
    }
    __syncthreads();
    for (int i = t; i < NPT * 3; i += NTH) rel[i] -= cen[(i / (GS * 3)) * 3 + i % 3];
    __syncthreads();

    int p = t & 127;
    float rx = rel[p * 3], ry = rel[p * 3 + 1], rz = rel[p * 3 + 2];
    int kq = t >> 7;      // 0..3: which k-quarter this thread fills

    // layer-1 + gelu + split for K-chunk kc into H buffer hb (16 values/thread)
    auto computeH = [&](int kc, int hb) {
        char* hbp = sm + SM_H(hb);
        #pragma unroll 4
        for (int i = 0; i < 16; i++) {
            int k = kq + i * 4;
            int kk = kc * KCH + k;
            float v = fmaf(rx, W1[kk], fmaf(ry, W1[HID + kk], fmaf(rz, W1[2 * HID + kk], b1[kk])));
            float h = gelu_exact(v);
            __nv_bfloat16 hi = __float2bfloat16(h);
            __nv_bfloat16 lo = __float2bfloat16(h - __bfloat162float(hi));
            uint32_t off = (uint32_t)(p * 128 + k * 2);
            off ^= (off >> 3) & 0x70;
            *(__nv_bfloat16*)(hbp + off) = hi;
            *(__nv_bfloat16*)(hbp + 16384 + off) = lo;
        }
    };

    // cp.async stage of one pre-swizzled W2 tile pair into buffer bi
    auto cp_issue = [&](int mc, int kc, int bi) {
        size_t tile = (size_t)(mc * NKC + kc) * TILE_B;
        const char* sh = g_w2hi + tile;
        const char* sl = g_w2lo + tile;
        uint32_t dh = smb + SM_W2(bi);
        #pragma unroll
        for (int i = 0; i < 2; i++) {
            uint32_t o = (uint32_t)(t * 16 + i * 8192);
            asm volatile("cp.async.cg.shared.global [%0], [%1], 16;"
                :: "r"(dh + o), "l"(__cvta_generic_to_global(sh + o)) : "memory");
            asm volatile("cp.async.cg.shared.global [%0], [%1], 16;"
                :: "r"(dh + 16384 + o), "l"(__cvta_generic_to_global(sl + o)) : "memory");
        }
        asm volatile("cp.async.commit_group;" ::: "memory");
    };

    int m0w = (wid & 3) * 32;      // warp M offset (embed cols within 128)
    int n0w = (wid >> 2) * 32;     // warp N offset (points): 4 quadrants of 32

    for (int mc = 0; mc < 3; mc++) {
        float c[2][4][4];
        #pragma unroll
        for (int mf = 0; mf < 2; mf++)
            #pragma unroll
            for (int nf = 0; nf < 4; nf++)
                #pragma unroll
                for (int q = 0; q < 4; q++) c[mf][nf][q] = 0.f;

        cp_issue(mc, 0, 0);
        cp_issue(mc, 1, 1);
        computeH(0, 0);

        for (int kc = 0; kc < NKC; kc++) {
            int bi = kc & 1;
            if (kc < NKC - 1) { asm volatile("cp.async.wait_group 1;" ::: "memory"); }
            else              { asm volatile("cp.async.wait_group 0;" ::: "memory"); }
            __syncthreads();

            uint32_t wbase = smb + SM_W2(bi);
            uint32_t hbase = smb + SM_H(bi);
            #pragma unroll
            for (int ks = 0; ks < 4; ks++) {
                uint32_t ahi[2][4], alo[2][4];
                #pragma unroll
                for (int mf = 0; mf < 2; mf++) {
                    uint32_t offA = (uint32_t)((m0w + mf * 16 + (lane & 15)) * 128
                                   + ks * 32 + ((lane >> 4) << 4));
                    offA ^= (offA >> 3) & 0x70;
                    ldmx4(ahi[mf], wbase + offA);
                    ldmx4(alo[mf], wbase + 16384 + offA);
                }
                #pragma unroll
                for (int nf = 0; nf < 4; nf++) {
                    uint32_t bhi[2], blo[2];
                    uint32_t offB = (uint32_t)((n0w + nf * 8 + (lane & 7)) * 128
                                   + ks * 32 + (((lane >> 3) & 1) << 4));
                    offB ^= (offB >> 3) & 0x70;
                    ldmx2(bhi, hbase + offB);
                    ldmx2(blo, hbase + 16384 + offB);
                    #pragma unroll
                    for (int mf = 0; mf < 2; mf++) {
                        mma16816(c[mf][nf], ahi[mf], bhi);
                        mma16816(c[mf][nf], ahi[mf], blo);
                        mma16816(c[mf][nf], alo[mf], bhi);
                    }
                }
            }
            __syncthreads();

            if (kc + 2 < NKC) cp_issue(mc, kc + 2, bi);
            if (kc + 1 < NKC) computeH(kc + 1, (kc + 1) & 1);
        }

        // epilogue: bias + gelu + group max (quad shuffle) + center proj
        #pragma unroll
        for (int mf = 0; mf < 2; mf++) {
            int row0 = mc * 128 + m0w + mf * 16 + (lane >> 2);
            int row1 = row0 + 8;
            float bias0 = b2[row0], bias1 = b2[row1];
            #pragma unroll
            for (int g = 0; g < 2; g++) {
                float va = -1e30f, vb = -1e30f;
                #pragma unroll
                for (int q = 0; q < 2; q++) {
                    float* cc = c[mf][2 * g + q];
                    va = fmaxf(va, fmaxf(gelu_exact(cc[0] + bias0), gelu_exact(cc[1] + bias0)));
                    vb = fmaxf(vb, fmaxf(gelu_exact(cc[2] + bias1), gelu_exact(cc[3] + bias1)));
                }
                va = fmaxf(va, __shfl_xor_sync(0xffffffffu, va, 1));
                va = fmaxf(va, __shfl_xor_sync(0xffffffffu, va, 2));
                vb = fmaxf(vb, __shfl_xor_sync(0xffffffffu, vb, 1));
                vb = fmaxf(vb, __shfl_xor_sync(0xffffffffu, vb, 2));
                if ((lane & 3) == 0) {
                    int gl = (wid >> 2) * 2 + g;
                    int gg = gbase + gl;
                    float c0_ = cen[gl * 3], c1_ = cen[gl * 3 + 1], c2_ = cen[gl * 3 + 2];
                    out[TOK_OFF + ((size_t)b * GG + gg) * ED + row0] =
                        va + c0_ * Wc[row0] + c1_ * Wc[ED + row0] + c2_ * Wc[2 * ED + row0] + bc[row0];
                    out[TOK_OFF + ((size_t)b * GG + gg) * ED + row1] =
                        vb + c0_ * Wc[row1] + c1_ * Wc[ED + row1] + c2_ * Wc[2 * ED + row1] + bc[row1];
                }
            }
        }
        __syncthreads();
    }
}

extern "C" void kernel_launch(void* const* d_in, const int* in_sizes, int n_in,
                              void* d_out, int out_size) {
    const float* xyz = (const float*)d_in[0];
    const float* W1  = (const float*)d_in[1];
    const float* b1  = (const float*)d_in[2];
    const float* W2  = (const float*)d_in[3];
    const float* b2  = (const float*)d_in[4];
    const float* Wc  = (const float*)d_in[5];
    const float* bc  = (const float*)d_in[6];
    float* out = (float*)d_out;

    const int sort_smem = NN * 8;
    cudaFuncSetAttribute(k_sort, cudaFuncAttributeMaxDynamicSharedMemorySize, sort_smem);
    cudaFuncSetAttribute(k_gemm, cudaFuncAttributeMaxDynamicSharedMemorySize, SM_TOTAL);

    k_minmax<<<BB, 256>>>(xyz);
    k_sort<<<BB, 1024, sort_smem>>>(xyz, out, out_size);
    k_prep<<<(HID * ED + 255) / 256, 256>>>(W2);
    k_gemm<<<BB * NN / NPT, NTH, SM_TOTAL>>>(xyz, W1, b1, b2, Wc, bc, out, out_size);
}

// round 11
// speedup vs baseline: 1.6057x; 1.1379x over previous
#include <cuda_runtime.h>
#include <cuda_bf16.h>
#include <cstdint>

#define BB   16
#define NN   16384
#define GS   16
#define GG   1024
#define HID  768
#define ED   384

// output layout (floats): tokens | centers | group_idx(as float)
#define TOK_OFF 0
#define CEN_OFF (BB*GG*ED)
#define IDX_OFF (CEN_OFF + BB*GG*3)
#define TOT_SZ  (IDX_OFF + BB*GG*GS)

// GEMM tiling
#define NPT 128                  // points per CTA (8 groups)
#define KCH 64                   // K chunk
#define NKC (HID/KCH)            // 12
#define TILE_B 16384             // one 128x64 bf16 tile
#define NTH 512                  // threads per CTA (16 warps)

// smem layout (bytes)
#define SM_W2(bi) ((bi)*32768)            // hi +0, lo +16384
#define SM_H(bi)  (65536 + (bi)*32768)    // hi +0, lo +16384
#define SM_REL    131072                  // 384 floats
#define SM_CEN    132608                  // 24 floats
#define SM_TOTAL  132736

__device__ float g_mm[BB * 6];
__device__ int   g_sidx[BB * NN];
__device__ __align__(16) char g_w2hi[3 * NKC * TILE_B];
__device__ __align__(16) char g_w2lo[3 * NKC * TILE_B];

__device__ __forceinline__ float gelu_exact(float x) {
    return 0.5f * x * (1.0f + erff(x * 0.70710678118654752f));
}
__device__ __forceinline__ int part1by2_10(int v) {
    v &= 1023;
    v = (v | (v << 16)) & 50331903;
    v = (v | (v << 8))  & 50393103;
    v = (v | (v << 4))  & 51130563;
    v = (v | (v << 2))  & 153391689;
    return v;
}
__device__ __forceinline__ uint32_t smem_u32(const void* p) {
    uint32_t a;
    asm("{ .reg .u64 t; cvta.to.shared.u64 t, %1; cvt.u32.u64 %0, t; }" : "=r"(a) : "l"(p));
    return a;
}
__device__ __forceinline__ void ldmx4(uint32_t* r, uint32_t a) {
    asm volatile("ldmatrix.sync.aligned.m8n8.x4.shared.b16 {%0,%1,%2,%3}, [%4];"
        : "=r"(r[0]), "=r"(r[1]), "=r"(r[2]), "=r"(r[3]) : "r"(a));
}
__device__ __forceinline__ void mma16816(float* c, const uint32_t* a, const uint32_t* b) {
    asm volatile(
        "mma.sync.aligned.m16n8k16.row.col.f32.bf16.bf16.f32 "
        "{%0,%1,%2,%3}, {%4,%5,%6,%7}, {%8,%9}, {%0,%1,%2,%3};"
        : "+f"(c[0]), "+f"(c[1]), "+f"(c[2]), "+f"(c[3])
        : "r"(a[0]), "r"(a[1]), "r"(a[2]), "r"(a[3]), "r"(b[0]), "r"(b[1]));
}
__device__ __forceinline__ uint32_t pack_bf2(__nv_bfloat16 a, __nv_bfloat16 b) {
    return (uint32_t)__bfloat16_as_ushort(a) | ((uint32_t)__bfloat16_as_ushort(b) << 16);
}

// ---------------- Kernel A: per-batch min/max (FROZEN) ----------------
__global__ void k_minmax(const float* __restrict__ xyz) {
    int b = blockIdx.x;
    int t = threadIdx.x;
    const float* p = xyz + (size_t)b * NN * 3;
    float mn0 = 1e30f, mn1 = 1e30f, mn2 = 1e30f;
    float mx0 = -1e30f, mx1 = -1e30f, mx2 = -1e30f;
    for (int i = t; i < NN; i += blockDim.x) {
        float v0 = p[i * 3], v1 = p[i * 3 + 1], v2 = p[i * 3 + 2];
        mn0 = fminf(mn0, v0); mx0 = fmaxf(mx0, v0);
        mn1 = fminf(mn1, v1); mx1 = fmaxf(mx1, v1);
        mn2 = fminf(mn2, v2); mx2 = fmaxf(mx2, v2);
    }
    __shared__ float s[6][256];
    s[0][t] = mn0; s[1][t] = mn1; s[2][t] = mn2;
    s[3][t] = mx0; s[4][t] = mx1; s[5][t] = mx2;
    __syncthreads();
    for (int w = 128; w > 0; w >>= 1) {
        if (t < w) {
            #pragma unroll
            for (int c = 0; c < 3; c++) {
                s[c][t]     = fminf(s[c][t],     s[c][t + w]);
                s[c + 3][t] = fmaxf(s[c + 3][t], s[c + 3][t + w]);
            }
        }
        __syncthreads();
    }
    if (t < 6) g_mm[b * 6 + t] = s[t][0];
}

// ---------------- Kernel B: morton + stable bitonic argsort (FROZEN) ----------------
__global__ void k_sort(const float* __restrict__ xyz, float* __restrict__ out, int out_size) {
    extern __shared__ unsigned long long keys[];
    int b = blockIdx.x;
    int t = threadIdx.x;
    float mn0 = g_mm[b * 6 + 0], mn1 = g_mm[b * 6 + 1], mn2 = g_mm[b * 6 + 2];
    float s0 = fmaxf(__fsub_rn(g_mm[b * 6 + 3], mn0), 1e-6f);
    float s1 = fmaxf(__fsub_rn(g_mm[b * 6 + 4], mn1), 1e-6f);
    float s2 = fmaxf(__fsub_rn(g_mm[b * 6 + 5], mn2), 1e-6f);
    float r0 = __fdiv_rn(1.0f, s0);
    float r1 = __fdiv_rn(1.0f, s1);
    float r2 = __fdiv_rn(1.0f, s2);
    const float* p = xyz + (size_t)b * NN * 3;

    for (int i = t; i < NN; i += blockDim.x) {
        float u0 = __fmul_rn(__fsub_rn(p[i * 3],     mn0), r0);
        float u1 = __fmul_rn(__fsub_rn(p[i * 3 + 1], mn1), r1);
        float u2 = __fmul_rn(__fsub_rn(p[i * 3 + 2], mn2), r2);
        int q0 = min(max(__float2int_rn(__fmul_rn(u0, 1023.0f)), 0), 1023);
        int q1 = min(max(__float2int_rn(__fmul_rn(u1, 1023.0f)), 0), 1023);
        int q2 = min(max(__float2int_rn(__fmul_rn(u2, 1023.0f)), 0), 1023);
        int code = part1by2_10(q0) | (part1by2_10(q1) << 1) | (part1by2_10(q2) << 2);
        keys[i] = ((unsigned long long)(unsigned)code << 14) | (unsigned long long)i;
    }
    __syncthreads();

    for (int k = 2; k <= NN; k <<= 1) {
        for (int j = k >> 1; j > 0; j >>= 1) {
            for (int i = t; i < NN; i += blockDim.x) {
                int ixj = i ^ j;
                if (ixj > i) {
                    unsigned long long a = keys[i], c = keys[ixj];
                    bool up = ((i & k) == 0);
                    if ((a > c) == up) { keys[i] = c; keys[ixj] = a; }
                }
            }
            __syncthreads();
        }
    }

    for (int i = t; i < NN; i += blockDim.x) {
        int si = (int)(keys[i] & 16383ULL);
        g_sidx[b * NN + i] = si;
        if (out_size >= TOT_SZ) out[IDX_OFF + b * NN + i] = (float)si;
    }
}

// ---------------- Kernel P: W2 -> bf16 hi/lo transposed + swizzled tiles ----------------
__global__ void k_prep(const float* __restrict__ W2) {
    int idx = blockIdx.x * 256 + threadIdx.x;
    if (idx >= HID * ED) return;
    int k = idx / ED, n = idx - k * ED;
    float w = W2[idx];
    __nv_bfloat16 hi = __float2bfloat16(w);
    __nv_bfloat16 lo = __float2bfloat16(w - __bfloat162float(hi));
    int mc = n >> 7, row = n & 127, kc = k >> 6, col = k & 63;
    uint32_t off = (uint32_t)(row * 128 + col * 2);
    off ^= (off >> 3) & 0x70;
    size_t tile = (size_t)(mc * NKC + kc) * TILE_B;
    *(__nv_bfloat16*)(g_w2hi + tile + off) = hi;
    *(__nv_bfloat16*)(g_w2lo + tile + off) = lo;
}

// ---------------- Kernel C: fused gather + MLP via mma.sync split-bf16, 16 warps ----------------
__global__ void __launch_bounds__(NTH, 1) k_gemm(
    const float* __restrict__ xyz,
    const float* __restrict__ W1, const float* __restrict__ b1,
    const float* __restrict__ b2,
    const float* __restrict__ Wc, const float* __restrict__ bc,
    float* __restrict__ out, int out_size)
{
    extern __shared__ char sm[];
    uint32_t smb = smem_u32(sm);
    float* rel = (float*)(sm + SM_REL);
    float* cen = (float*)(sm + SM_CEN);

    int t = threadIdx.x, wid = t >> 5, lane = t & 31;
    int blk = blockIdx.x;                 // 2048
    int b = blk >> 7;
    int chunk = blk & 127;
    int gbase = chunk * 8;
    int m0 = chunk * NPT;

    // gather sorted points
    if (t < NPT) {
        int si = g_sidx[b * NN + m0 + t];
        const float* pp = xyz + ((size_t)b * NN + si) * 3;
        rel[t * 3 + 0] = pp[0];
        rel[t * 3 + 1] = pp[1];
        rel[t * 3 + 2] = pp[2];
    }
    __syncthreads();
    if (t < 24) {
        int g = t / 3, cc = t - g * 3;
        float sum = 0.f;
        #pragma unroll
        for (int p = 0; p < GS; p++) sum += rel[(g * GS + p) * 3 + cc];
        float cv = sum * (1.0f / GS);
        cen[t] = cv;
        if (out_size >= CEN_OFF + BB * GG * 3)
            out[CEN_OFF + ((size_t)b * GG + gbase + g) * 3 + cc] = cv;
    }
    __syncthreads();
    for (int i = t; i < NPT * 3; i += NTH) rel[i] -= cen[(i / (GS * 3)) * 3 + i % 3];
    __syncthreads();

    int p = t & 127;
    float rx = rel[p * 3], ry = rel[p * 3 + 1], rz = rel[p * 3 + 2];
    int kq = t >> 7;                      // 0..3: contiguous 16-k slice per thread
    uint32_t hswz = (uint32_t)((p & 7) << 4);
    uint32_t hrow = (uint32_t)(p * 128);

    // layer-1 + gelu + split for K-chunk kc into H buffer hb
    // contiguous k -> float4 W1 loads + uint4 H stores (4 STS.128/thread)
    auto computeH = [&](int kc, int hb) {
        char* hbp = sm + SM_H(hb);
        #pragma unroll
        for (int i = 0; i < 2; i++) {
            int k  = kq * 16 + i * 8;
            int kk = kc * KCH + k;
            float4 wa0 = *(const float4*)(W1 + kk);
            float4 wa1 = *(const float4*)(W1 + kk + 4);
            float4 wb0 = *(const float4*)(W1 + HID + kk);
            float4 wb1 = *(const float4*)(W1 + HID + kk + 4);
            float4 wc0 = *(const float4*)(W1 + 2 * HID + kk);
            float4 wc1 = *(const float4*)(W1 + 2 * HID + kk + 4);
            float4 bb0 = *(const float4*)(b1 + kk);
            float4 bb1 = *(const float4*)(b1 + kk + 4);
            float h[8];
            h[0] = gelu_exact(fmaf(rx, wa0.x, fmaf(ry, wb0.x, fmaf(rz, wc0.x, bb0.x))));
            h[1] = gelu_exact(fmaf(rx, wa0.y, fmaf(ry, wb0.y, fmaf(rz, wc0.y, bb0.y))));
            h[2] = gelu_exact(fmaf(rx, wa0.z, fmaf(ry, wb0.z, fmaf(rz, wc0.z, bb0.z))));
            h[3] = gelu_exact(fmaf(rx, wa0.w, fmaf(ry, wb0.w, fmaf(rz, wc0.w, bb0.w))));
            h[4] = gelu_exact(fmaf(rx, wa1.x, fmaf(ry, wb1.x, fmaf(rz, wc1.x, bb1.x))));
            h[5] = gelu_exact(fmaf(rx, wa1.y, fmaf(ry, wb1.y, fmaf(rz, wc1.y, bb1.y))));
            h[6] = gelu_exact(fmaf(rx, wa1.z, fmaf(ry, wb1.z, fmaf(rz, wc1.z, bb1.z))));
            h[7] = gelu_exact(fmaf(rx, wa1.w, fmaf(ry, wb1.w, fmaf(rz, wc1.w, bb1.w))));
            uint32_t hw[4], lw[4];
            #pragma unroll
            for (int j = 0; j < 4; j++) {
                __nv_bfloat16 e0 = __float2bfloat16(h[2 * j]);
                __nv_bfloat16 e1 = __float2bfloat16(h[2 * j + 1]);
                hw[j] = pack_bf2(e0, e1);
                __nv_bfloat16 l0 = __float2bfloat16(h[2 * j]     - __bfloat162float(e0));
                __nv_bfloat16 l1 = __float2bfloat16(h[2 * j + 1] - __bfloat162float(e1));
                lw[j] = pack_bf2(l0, l1);
            }
            uint32_t off = hrow + (((uint32_t)(k * 2)) ^ hswz);
            *(uint4*)(hbp + off)         = make_uint4(hw[0], hw[1], hw[2], hw[3]);
            *(uint4*)(hbp + 16384 + off) = make_uint4(lw[0], lw[1], lw[2], lw[3]);
        }
    };

    // cp.async stage of one pre-swizzled W2 tile pair into buffer bi
    auto cp_issue = [&](int mc, int kc, int bi) {
        size_t tile = (size_t)(mc * NKC + kc) * TILE_B;
        const char* sh = g_w2hi + tile;
        const char* sl = g_w2lo + tile;
        uint32_t dh = smb + SM_W2(bi);
        #pragma unroll
        for (int i = 0; i < 2; i++) {
            uint32_t o = (uint32_t)(t * 16 + i * 8192);
            asm volatile("cp.async.cg.shared.global [%0], [%1], 16;"
                :: "r"(dh + o), "l"(__cvta_generic_to_global(sh + o)) : "memory");
            asm volatile("cp.async.cg.shared.global [%0], [%1], 16;"
                :: "r"(dh + 16384 + o), "l"(__cvta_generic_to_global(sl + o)) : "memory");
        }
        asm volatile("cp.async.commit_group;" ::: "memory");
    };

    int m0w = (wid & 3) * 32;      // warp M offset (embed cols within 128)
    int n0w = (wid >> 2) * 32;     // warp N offset (points): 4 quadrants of 32

    for (int mc = 0; mc < 3; mc++) {
        float c[2][4][4];
        #pragma unroll
        for (int mf = 0; mf < 2; mf++)
            #pragma unroll
            for (int nf = 0; nf < 4; nf++)
                #pragma unroll
                for (int q = 0; q < 4; q++) c[mf][nf][q] = 0.f;

        cp_issue(mc, 0, 0);
        cp_issue(mc, 1, 1);
        computeH(0, 0);

        for (int kc = 0; kc < NKC; kc++) {
            int bi = kc & 1;
            if (kc < NKC - 1) { asm volatile("cp.async.wait_group 1;" ::: "memory"); }
            else              { asm volatile("cp.async.wait_group 0;" ::: "memory"); }
            __syncthreads();

            uint32_t wbase = smb + SM_W2(bi);
            uint32_t hbase = smb + SM_H(bi);
            #pragma unroll
            for (int ks = 0; ks < 4; ks++) {
                uint32_t ahi[2][4], alo[2][4];
                #pragma unroll
                for (int mf = 0; mf < 2; mf++) {
                    uint32_t offA = (uint32_t)((m0w + mf * 16 + (lane & 15)) * 128
                                   + ks * 32 + ((lane >> 4) << 4));
                    offA ^= (offA >> 3) & 0x70;
                    ldmx4(ahi[mf], wbase + offA);
                    ldmx4(alo[mf], wbase + 16384 + offA);
                }
                // B: paired ldmx4 -> frags (nf even k0,k1 | nf odd k0,k1)
                int gq = lane >> 3, nfs = gq >> 1, khl = (gq & 1) << 4, lb = lane & 7;
                #pragma unroll
                for (int nfp = 0; nfp < 2; nfp++) {
                    uint32_t offB = (uint32_t)((n0w + (nfp * 2 + nfs) * 8 + lb) * 128
                                   + ks * 32 + khl);
                    offB ^= (offB >> 3) & 0x70;
                    uint32_t bh[4], bl[4];
                    ldmx4(bh, hbase + offB);
                    ldmx4(bl, hbase + 16384 + offB);
                    #pragma unroll
                    for (int half = 0; half < 2; half++) {
                        int nf = nfp * 2 + half;
                        #pragma unroll
                        for (int mf = 0; mf < 2; mf++) {
                            mma16816(c[mf][nf], ahi[mf], bh + 2 * half);
                            mma16816(c[mf][nf], ahi[mf], bl + 2 * half);
                            mma16816(c[mf][nf], alo[mf], bh + 2 * half);
                        }
                    }
                }
            }
            __syncthreads();

            if (kc + 2 < NKC) cp_issue(mc, kc + 2, bi);
            if (kc + 1 < NKC) computeH(kc + 1, (kc + 1) & 1);
        }

        // epilogue: bias + gelu + group max (quad shuffle) + center proj
        #pragma unroll
        for (int mf = 0; mf < 2; mf++) {
            int row0 = mc * 128 + m0w + mf * 16 + (lane >> 2);
            int row1 = row0 + 8;
            float bias0 = b2[row0], bias1 = b2[row1];
            #pragma unroll
            for (int g = 0; g < 2; g++) {
                float va = -1e30f, vb = -1e30f;
                #pragma unroll
                for (int q = 0; q < 2; q++) {
                    float* cc = c[mf][2 * g + q];
                    va = fmaxf(va, fmaxf(gelu_exact(cc[0] + bias0), gelu_exact(cc[1] + bias0)));
                    vb = fmaxf(vb, fmaxf(gelu_exact(cc[2] + bias1), gelu_exact(cc[3] + bias1)));
                }
                va = fmaxf(va, __shfl_xor_sync(0xffffffffu, va, 1));
                va = fmaxf(va, __shfl_xor_sync(0xffffffffu, va, 2));
                vb = fmaxf(vb, __shfl_xor_sync(0xffffffffu, vb, 1));
                vb = fmaxf(vb, __shfl_xor_sync(0xffffffffu, vb, 2));
                if ((lane & 3) == 0) {
                    int gl = (wid >> 2) * 2 + g;
                    int gg = gbase + gl;
                    float c0_ = cen[gl * 3], c1_ = cen[gl * 3 + 1], c2_ = cen[gl * 3 + 2];
                    out[TOK_OFF + ((size_t)b * GG + gg) * ED + row0] =
                        va + c0_ * Wc[row0] + c1_ * Wc[ED + row0] + c2_ * Wc[2 * ED + row0] + bc[row0];
                    out[TOK_OFF + ((size_t)b * GG + gg) * ED + row1] =
                        vb + c0_ * Wc[row1] + c1_ * Wc[ED + row1] + c2_ * Wc[2 * ED + row1] + bc[row1];
                }
            }
        }
        __syncthreads();
    }
}

extern "C" void kernel_launch(void* const* d_in, const int* in_sizes, int n_in,
                              void* d_out, int out_size) {
    const float* xyz = (const float*)d_in[0];
    const float* W1  = (const float*)d_in[1];
    const float* b1  = (const float*)d_in[2];
    const float* W2  = (const float*)d_in[3];
    const float* b2  = (const float*)d_in[4];
    const float* Wc  = (const float*)d_in[5];
    const float* bc  = (const float*)d_in[6];
    float* out = (float*)d_out;

    const int sort_smem = NN * 8;
    cudaFuncSetAttribute(k_sort, cudaFuncAttributeMaxDynamicSharedMemorySize, sort_smem);
    cudaFuncSetAttribute(k_gemm, cudaFuncAttributeMaxDynamicSharedMemorySize, SM_TOTAL);

    k_minmax<<<BB, 256>>>(xyz);
    k_sort<<<BB, 1024, sort_smem>>>(xyz, out, out_size);
    k_prep<<<(HID * ED + 255) / 256, 256>>>(W2);
    k_gemm<<<BB * NN / NPT, NTH, SM_TOTAL>>>(xyz, W1, b1, b2, Wc, bc, out, out_size);
}

// round 12
// speedup vs baseline: 2.0314x; 1.2651x over previous
#include <cuda_runtime.h>
#include <cuda_bf16.h>
#include <cuda_fp16.h>
#include <cstdint>

#define BB   16
#define NN   16384
#define GS   16
#define GG   1024
#define HID  768
#define ED   384

// output layout (floats): tokens | centers | group_idx(as float)
#define TOK_OFF 0
#define CEN_OFF (BB*GG*ED)
#define IDX_OFF (CEN_OFF + BB*GG*3)
#define TOT_SZ  (IDX_OFF + BB*GG*GS)

// GEMM tiling
#define NPT 128                  // points per CTA (8 groups)
#define KCH 64                   // K chunk
#define NKC (HID/KCH)            // 12
#define TILE_B 16384             // one 128x64 fp16 tile
#define NTH 512                  // threads per CTA (16 warps)
#define W2SCALE 256.0f
#define INVW2SCALE (1.0f/256.0f)

// smem layout (bytes)
#define SM_W2(bi) ((bi)*32768)            // hi +0, lo +16384
#define SM_H(bi)  (65536 + (bi)*16384)    // single fp16 H tile per buffer
#define SM_REL    98304                   // 384 floats
#define SM_CEN    99840                   // 24 floats
#define SM_TOTAL  99968

__device__ float g_mm[BB * 6];
__device__ int   g_sidx[BB * NN];
__device__ __align__(16) char g_w2hi[3 * NKC * TILE_B];
__device__ __align__(16) char g_w2lo[3 * NKC * TILE_B];

__device__ __forceinline__ float gelu_exact(float x) {
    return 0.5f * x * (1.0f + erff(x * 0.70710678118654752f));
}
__device__ __forceinline__ int part1by2_10(int v) {
    v &= 1023;
    v = (v | (v << 16)) & 50331903;
    v = (v | (v << 8))  & 50393103;
    v = (v | (v << 4))  & 51130563;
    v = (v | (v << 2))  & 153391689;
    return v;
}
__device__ __forceinline__ uint32_t smem_u32(const void* p) {
    uint32_t a;
    asm("{ .reg .u64 t; cvta.to.shared.u64 t, %1; cvt.u32.u64 %0, t; }" : "=r"(a) : "l"(p));
    return a;
}
__device__ __forceinline__ void ldmx4(uint32_t* r, uint32_t a) {
    asm volatile("ldmatrix.sync.aligned.m8n8.x4.shared.b16 {%0,%1,%2,%3}, [%4];"
        : "=r"(r[0]), "=r"(r[1]), "=r"(r[2]), "=r"(r[3]) : "r"(a));
}
__device__ __forceinline__ void mma16816h(float* c, const uint32_t* a, const uint32_t* b) {
    asm volatile(
        "mma.sync.aligned.m16n8k16.row.col.f32.f16.f16.f32 "
        "{%0,%1,%2,%3}, {%4,%5,%6,%7}, {%8,%9}, {%0,%1,%2,%3};"
        : "+f"(c[0]), "+f"(c[1]), "+f"(c[2]), "+f"(c[3])
        : "r"(a[0]), "r"(a[1]), "r"(a[2]), "r"(a[3]), "r"(b[0]), "r"(b[1]));
}
__device__ __forceinline__ uint32_t pack_h2(__half a, __half b) {
    __half2 h2 = __halves2half2(a, b);
    return *(uint32_t*)&h2;
}

// ---------------- Kernel A: per-batch min/max (FROZEN) ----------------
__global__ void k_minmax(const float* __restrict__ xyz) {
    int b = blockIdx.x;
    int t = threadIdx.x;
    const float* p = xyz + (size_t)b * NN * 3;
    float mn0 = 1e30f, mn1 = 1e30f, mn2 = 1e30f;
    float mx0 = -1e30f, mx1 = -1e30f, mx2 = -1e30f;
    for (int i = t; i < NN; i += blockDim.x) {
        float v0 = p[i * 3], v1 = p[i * 3 + 1], v2 = p[i * 3 + 2];
        mn0 = fminf(mn0, v0); mx0 = fmaxf(mx0, v0);
        mn1 = fminf(mn1, v1); mx1 = fmaxf(mx1, v1);
        mn2 = fminf(mn2, v2); mx2 = fmaxf(mx2, v2);
    }
    __shared__ float s[6][256];
    s[0][t] = mn0; s[1][t] = mn1; s[2][t] = mn2;
    s[3][t] = mx0; s[4][t] = mx1; s[5][t] = mx2;
    __syncthreads();
    for (int w = 128; w > 0; w >>= 1) {
        if (t < w) {
            #pragma unroll
            for (int c = 0; c < 3; c++) {
                s[c][t]     = fminf(s[c][t],     s[c][t + w]);
                s[c + 3][t] = fmaxf(s[c + 3][t], s[c + 3][t + w]);
            }
        }
        __syncthreads();
    }
    if (t < 6) g_mm[b * 6 + t] = s[t][0];
}

// ---------------- Kernel B: morton + stable bitonic argsort (FROZEN) ----------------
__global__ void k_sort(const float* __restrict__ xyz, float* __restrict__ out, int out_size) {
    extern __shared__ unsigned long long keys[];
    int b = blockIdx.x;
    int t = threadIdx.x;
    float mn0 = g_mm[b * 6 + 0], mn1 = g_mm[b * 6 + 1], mn2 = g_mm[b * 6 + 2];
    float s0 = fmaxf(__fsub_rn(g_mm[b * 6 + 3], mn0), 1e-6f);
    float s1 = fmaxf(__fsub_rn(g_mm[b * 6 + 4], mn1), 1e-6f);
    float s2 = fmaxf(__fsub_rn(g_mm[b * 6 + 5], mn2), 1e-6f);
    float r0 = __fdiv_rn(1.0f, s0);
    float r1 = __fdiv_rn(1.0f, s1);
    float r2 = __fdiv_rn(1.0f, s2);
    const float* p = xyz + (size_t)b * NN * 3;

    for (int i = t; i < NN; i += blockDim.x) {
        float u0 = __fmul_rn(__fsub_rn(p[i * 3],     mn0), r0);
        float u1 = __fmul_rn(__fsub_rn(p[i * 3 + 1], mn1), r1);
        float u2 = __fmul_rn(__fsub_rn(p[i * 3 + 2], mn2), r2);
        int q0 = min(max(__float2int_rn(__fmul_rn(u0, 1023.0f)), 0), 1023);
        int q1 = min(max(__float2int_rn(__fmul_rn(u1, 1023.0f)), 0), 1023);
        int q2 = min(max(__float2int_rn(__fmul_rn(u2, 1023.0f)), 0), 1023);
        int code = part1by2_10(q0) | (part1by2_10(q1) << 1) | (part1by2_10(q2) << 2);
        keys[i] = ((unsigned long long)(unsigned)code << 14) | (unsigned long long)i;
    }
    __syncthreads();

    for (int k = 2; k <= NN; k <<= 1) {
        for (int j = k >> 1; j > 0; j >>= 1) {
            for (int i = t; i < NN; i += blockDim.x) {
                int ixj = i ^ j;
                if (ixj > i) {
                    unsigned long long a = keys[i], c = keys[ixj];
                    bool up = ((i & k) == 0);
                    if ((a > c) == up) { keys[i] = c; keys[ixj] = a; }
                }
            }
            __syncthreads();
        }
    }

    for (int i = t; i < NN; i += blockDim.x) {
        int si = (int)(keys[i] & 16383ULL);
        g_sidx[b * NN + i] = si;
        if (out_size >= TOT_SZ) out[IDX_OFF + b * NN + i] = (float)si;
    }
}

// ---------------- Kernel P: 256*W2 -> fp16 hi/lo transposed + swizzled tiles ----------------
__global__ void k_prep(const float* __restrict__ W2) {
    int idx = blockIdx.x * 256 + threadIdx.x;
    if (idx >= HID * ED) return;
    int k = idx / ED, n = idx - k * ED;
    float w = W2[idx] * W2SCALE;          // exact scale, keeps lo in fp16-normal range
    __half hi = __float2half(w);
    __half lo = __float2half(w - __half2float(hi));
    int mc = n >> 7, row = n & 127, kc = k >> 6, col = k & 63;
    uint32_t off = (uint32_t)(row * 128 + col * 2);
    off ^= (off >> 3) & 0x70;
    size_t tile = (size_t)(mc * NKC + kc) * TILE_B;
    *(__half*)(g_w2hi + tile + off) = hi;
    *(__half*)(g_w2lo + tile + off) = lo;
}

// ---------------- Kernel C: fused gather + MLP via mma.sync split-fp16, 16 warps ----------------
__global__ void __launch_bounds__(NTH, 1) k_gemm(
    const float* __restrict__ xyz,
    const float* __restrict__ W1, const float* __restrict__ b1,
    const float* __restrict__ b2,
    const float* __restrict__ Wc, const float* __restrict__ bc,
    float* __restrict__ out, int out_size)
{
    extern __shared__ char sm[];
    uint32_t smb = smem_u32(sm);
    float* rel = (float*)(sm + SM_REL);
    float* cen = (float*)(sm + SM_CEN);

    int t = threadIdx.x, wid = t >> 5, lane = t & 31;
    int blk = blockIdx.x;                 // 2048
    int b = blk >> 7;
    int chunk = blk & 127;
    int gbase = chunk * 8;
    int m0 = chunk * NPT;

    // gather sorted points
    if (t < NPT) {
        int si = g_sidx[b * NN + m0 + t];
        const float* pp = xyz + ((size_t)b * NN + si) * 3;
        rel[t * 3 + 0] = pp[0];
        rel[t * 3 + 1] = pp[1];
        rel[t * 3 + 2] = pp[2];
    }
    __syncthreads();
    if (t < 24) {
        int g = t / 3, cc = t - g * 3;
        float sum = 0.f;
        #pragma unroll
        for (int p = 0; p < GS; p++) sum += rel[(g * GS + p) * 3 + cc];
        float cv = sum * (1.0f / GS);
        cen[t] = cv;
        if (out_size >= CEN_OFF + BB * GG * 3)
            out[CEN_OFF + ((size_t)b * GG + gbase + g) * 3 + cc] = cv;
    }
    __syncthreads();
    for (int i = t; i < NPT * 3; i += NTH) rel[i] -= cen[(i / (GS * 3)) * 3 + i % 3];
    __syncthreads();

    int p = t & 127;
    float rx = rel[p * 3], ry = rel[p * 3 + 1], rz = rel[p * 3 + 2];
    int kq = t >> 7;                      // 0..3: contiguous 16-k slice per thread
    uint32_t hswz = (uint32_t)((p & 7) << 4);
    uint32_t hrow = (uint32_t)(p * 128);

    // layer-1 + gelu -> single fp16 H tile (1 STS.128 per 8 values)
    auto computeH = [&](int kc, int hb) {
        char* hbp = sm + SM_H(hb);
        #pragma unroll
        for (int i = 0; i < 2; i++) {
            int k  = kq * 16 + i * 8;
            int kk = kc * KCH + k;
            float4 wa0 = *(const float4*)(W1 + kk);
            float4 wa1 = *(const float4*)(W1 + kk + 4);
            float4 wb0 = *(const float4*)(W1 + HID + kk);
            float4 wb1 = *(const float4*)(W1 + HID + kk + 4);
            float4 wc0 = *(const float4*)(W1 + 2 * HID + kk);
            float4 wc1 = *(const float4*)(W1 + 2 * HID + kk + 4);
            float4 bb0 = *(const float4*)(b1 + kk);
            float4 bb1 = *(const float4*)(b1 + kk + 4);
            float h[8];
            h[0] = gelu_exact(fmaf(rx, wa0.x, fmaf(ry, wb0.x, fmaf(rz, wc0.x, bb0.x))));
            h[1] = gelu_exact(fmaf(rx, wa0.y, fmaf(ry, wb0.y, fmaf(rz, wc0.y, bb0.y))));
            h[2] = gelu_exact(fmaf(rx, wa0.z, fmaf(ry, wb0.z, fmaf(rz, wc0.z, bb0.z))));
            h[3] = gelu_exact(fmaf(rx, wa0.w, fmaf(ry, wb0.w, fmaf(rz, wc0.w, bb0.w))));
            h[4] = gelu_exact(fmaf(rx, wa1.x, fmaf(ry, wb1.x, fmaf(rz, wc1.x, bb1.x))));
            h[5] = gelu_exact(fmaf(rx, wa1.y, fmaf(ry, wb1.y, fmaf(rz, wc1.y, bb1.y))));
            h[6] = gelu_exact(fmaf(rx, wa1.z, fmaf(ry, wb1.z, fmaf(rz, wc1.z, bb1.z))));
            h[7] = gelu_exact(fmaf(rx, wa1.w, fmaf(ry, wb1.w, fmaf(rz, wc1.w, bb1.w))));
            uint32_t hw[4];
            #pragma unroll
            for (int j = 0; j < 4; j++)
                hw[j] = pack_h2(__float2half(h[2 * j]), __float2half(h[2 * j + 1]));
            uint32_t off = hrow + (((uint32_t)(k * 2)) ^ hswz);
            *(uint4*)(hbp + off) = make_uint4(hw[0], hw[1], hw[2], hw[3]);
        }
    };

    // cp.async stage of one pre-swizzled W2 tile pair into buffer bi
    auto cp_issue = [&](int mc, int kc, int bi) {
        size_t tile = (size_t)(mc * NKC + kc) * TILE_B;
        const char* sh = g_w2hi + tile;
        const char* sl = g_w2lo + tile;
        uint32_t dh = smb + SM_W2(bi);
        #pragma unroll
        for (int i = 0; i < 2; i++) {
            uint32_t o = (uint32_t)(t * 16 + i * 8192);
            asm volatile("cp.async.cg.shared.global [%0], [%1], 16;"
                :: "r"(dh + o), "l"(__cvta_generic_to_global(sh + o)) : "memory");
            asm volatile("cp.async.cg.shared.global [%0], [%1], 16;"
                :: "r"(dh + 16384 + o), "l"(__cvta_generic_to_global(sl + o)) : "memory");
        }
        asm volatile("cp.async.commit_group;" ::: "memory");
    };

    int m0w = (wid & 3) * 32;      // warp M offset (embed cols within 128)
    int n0w = (wid >> 2) * 32;     // warp N offset (points): 4 quadrants of 32

    for (int mc = 0; mc < 3; mc++) {
        float c[2][4][4];
        #pragma unroll
        for (int mf = 0; mf < 2; mf++)
            #pragma unroll
            for (int nf = 0; nf < 4; nf++)
                #pragma unroll
                for (int q = 0; q < 4; q++) c[mf][nf][q] = 0.f;

        cp_issue(mc, 0, 0);
        cp_issue(mc, 1, 1);
        computeH(0, 0);

        for (int kc = 0; kc < NKC; kc++) {
            int bi = kc & 1;
            if (kc < NKC - 1) { asm volatile("cp.async.wait_group 1;" ::: "memory"); }
            else              { asm volatile("cp.async.wait_group 0;" ::: "memory"); }
            __syncthreads();

            uint32_t wbase = smb + SM_W2(bi);
            uint32_t hbase = smb + SM_H(bi);
            #pragma unroll
            for (int ks = 0; ks < 4; ks++) {
                uint32_t ahi[2][4], alo[2][4];
                #pragma unroll
                for (int mf = 0; mf < 2; mf++) {
                    uint32_t offA = (uint32_t)((m0w + mf * 16 + (lane & 15)) * 128
                                   + ks * 32 + ((lane >> 4) << 4));
                    offA ^= (offA >> 3) & 0x70;
                    ldmx4(ahi[mf], wbase + offA);
                    ldmx4(alo[mf], wbase + 16384 + offA);
                }
                // B: paired ldmx4 -> frags (nf even k0,k1 | nf odd k0,k1)
                int gq = lane >> 3, nfs = gq >> 1, khl = (gq & 1) << 4, lb = lane & 7;
                #pragma unroll
                for (int nfp = 0; nfp < 2; nfp++) {
                    uint32_t offB = (uint32_t)((n0w + (nfp * 2 + nfs) * 8 + lb) * 128
                                   + ks * 32 + khl);
                    offB ^= (offB >> 3) & 0x70;
                    uint32_t bh[4];
                    ldmx4(bh, hbase + offB);
                    #pragma unroll
                    for (int half = 0; half < 2; half++) {
                        int nf = nfp * 2 + half;
                        #pragma unroll
                        for (int mf = 0; mf < 2; mf++) {
                            mma16816h(c[mf][nf], ahi[mf], bh + 2 * half);
                            mma16816h(c[mf][nf], alo[mf], bh + 2 * half);
                        }
                    }
                }
            }
            __syncthreads();

            if (kc + 2 < NKC) cp_issue(mc, kc + 2, bi);
            if (kc + 1 < NKC) computeH(kc + 1, (kc + 1) & 1);
        }

        // epilogue: unscale + bias + gelu + group max (quad shuffle) + center proj
        #pragma unroll
        for (int mf = 0; mf < 2; mf++) {
            int row0 = mc * 128 + m0w + mf * 16 + (lane >> 2);
            int row1 = row0 + 8;
            float bias0 = b2[row0], bias1 = b2[row1];
            #pragma unroll
            for (int g = 0; g < 2; g++) {
                float va = -1e30f, vb = -1e30f;
                #pragma unroll
                for (int q = 0; q < 2; q++) {
                    float* cc = c[mf][2 * g + q];
                    va = fmaxf(va, fmaxf(gelu_exact(fmaf(cc[0], INVW2SCALE, bias0)),
                                         gelu_exact(fmaf(cc[1], INVW2SCALE, bias0))));
                    vb = fmaxf(vb, fmaxf(gelu_exact(fmaf(cc[2], INVW2SCALE, bias1)),
                                         gelu_exact(fmaf(cc[3], INVW2SCALE, bias1))));
                }
                va = fmaxf(va, __shfl_xor_sync(0xffffffffu, va, 1));
                va = fmaxf(va, __shfl_xor_sync(0xffffffffu, va, 2));
                vb = fmaxf(vb, __shfl_xor_sync(0xffffffffu, vb, 1));
                vb = fmaxf(vb, __shfl_xor_sync(0xffffffffu, vb, 2));
                if ((lane & 3) == 0) {
                    int gl = (wid >> 2) * 2 + g;
                    int gg = gbase + gl;
                    float c0_ = cen[gl * 3], c1_ = cen[gl * 3 + 1], c2_ = cen[gl * 3 + 2];
                    out[TOK_OFF + ((size_t)b * GG + gg) * ED + row0] =
                        va + c0_ * Wc[row0] + c1_ * Wc[ED + row0] + c2_ * Wc[2 * ED + row0] + bc[row0];
                    out[TOK_OFF + ((size_t)b * GG + gg) * ED + row1] =
                        vb + c0_ * Wc[row1] + c1_ * Wc[ED + row1] + c2_ * Wc[2 * ED + row1] + bc[row1];
                }
            }
        }
        __syncthreads();
    }
}

extern "C" void kernel_launch(void* const* d_in, const int* in_sizes, int n_in,
                              void* d_out, int out_size) {
    const float* xyz = (const float*)d_in[0];
    const float* W1  = (const float*)d_in[1];
    const float* b1  = (const float*)d_in[2];
    const float* W2  = (const float*)d_in[3];
    const float* b2  = (const float*)d_in[4];
    const float* Wc  = (const float*)d_in[5];
    const float* bc  = (const float*)d_in[6];
    float* out = (float*)d_out;

    const int sort_smem = NN * 8;
    cudaFuncSetAttribute(k_sort, cudaFuncAttributeMaxDynamicSharedMemorySize, sort_smem);
    cudaFuncSetAttribute(k_gemm, cudaFuncAttributeMaxDynamicSharedMemorySize, SM_TOTAL);

    k_minmax<<<BB, 256>>>(xyz);
    k_sort<<<BB, 1024, sort_smem>>>(xyz, out, out_size);
    k_prep<<<(HID * ED + 255) / 256, 256>>>(W2);
    k_gemm<<<BB * NN / NPT, NTH, SM_TOTAL>>>(xyz, W1, b1, b2, Wc, bc, out, out_size);
}

// round 13
// speedup vs baseline: 2.6622x; 1.3106x over previous
#include <cuda_runtime.h>
#include <cuda_bf16.h>
#include <cuda_fp16.h>
#include <cstdint>

#define BB   16
#define NN   16384
#define GS   16
#define GG   1024
#define HID  768
#define ED   384

// output layout (floats): tokens | centers | group_idx(as float)
#define TOK_OFF 0
#define CEN_OFF (BB*GG*ED)
#define IDX_OFF (CEN_OFF + BB*GG*3)
#define TOT_SZ  (IDX_OFF + BB*GG*GS)

// GEMM tiling
#define NPT 128                  // points per CTA (8 groups)
#define KCH 64                   // K chunk
#define NKC (HID/KCH)            // 12
#define TILE_B 16384             // one 128x64 fp16 tile
#define NTH 512                  // threads per CTA (16 warps)
#define W2SCALE 256.0f
#define INVW2SCALE (1.0f/256.0f)

// smem: per stage W2hi(16K) | W2lo(16K) | H(16K); two stages
#define STAGE_B 49152
#define SM_REL    98304                   // 384 floats
#define SM_CEN    99840                   // 24 floats
#define SM_TOTAL  99968

__device__ float g_mm[BB * 6];
__device__ int   g_sidx[BB * NN];
__device__ __align__(16) char g_w2hi[3 * NKC * TILE_B];
__device__ __align__(16) char g_w2lo[3 * NKC * TILE_B];
__device__ __align__(16) char g_h[(size_t)2048 * NKC * TILE_B];   // 402 MB H tiles

__device__ __forceinline__ float gelu_exact(float x) {
    return 0.5f * x * (1.0f + erff(x * 0.70710678118654752f));
}
__device__ __forceinline__ int part1by2_10(int v) {
    v &= 1023;
    v = (v | (v << 16)) & 50331903;
    v = (v | (v << 8))  & 50393103;
    v = (v | (v << 4))  & 51130563;
    v = (v | (v << 2))  & 153391689;
    return v;
}
__device__ __forceinline__ uint32_t smem_u32(const void* p) {
    uint32_t a;
    asm("{ .reg .u64 t; cvta.to.shared.u64 t, %1; cvt.u32.u64 %0, t; }" : "=r"(a) : "l"(p));
    return a;
}
__device__ __forceinline__ void ldmx4(uint32_t* r, uint32_t a) {
    asm volatile("ldmatrix.sync.aligned.m8n8.x4.shared.b16 {%0,%1,%2,%3}, [%4];"
        : "=r"(r[0]), "=r"(r[1]), "=r"(r[2]), "=r"(r[3]) : "r"(a));
}
__device__ __forceinline__ void mma16816h(float* c, const uint32_t* a, const uint32_t* b) {
    asm volatile(
        "mma.sync.aligned.m16n8k16.row.col.f32.f16.f16.f32 "
        "{%0,%1,%2,%3}, {%4,%5,%6,%7}, {%8,%9}, {%0,%1,%2,%3};"
        : "+f"(c[0]), "+f"(c[1]), "+f"(c[2]), "+f"(c[3])
        : "r"(a[0]), "r"(a[1]), "r"(a[2]), "r"(a[3]), "r"(b[0]), "r"(b[1]));
}
__device__ __forceinline__ uint32_t pack_h2(__half a, __half b) {
    __half2 h2 = __halves2half2(a, b);
    return *(uint32_t*)&h2;
}

// ---------------- Kernel A: per-batch min/max (FROZEN) ----------------
__global__ void k_minmax(const float* __restrict__ xyz) {
    int b = blockIdx.x;
    int t = threadIdx.x;
    const float* p = xyz + (size_t)b * NN * 3;
    float mn0 = 1e30f, mn1 = 1e30f, mn2 = 1e30f;
    float mx0 = -1e30f, mx1 = -1e30f, mx2 = -1e30f;
    for (int i = t; i < NN; i += blockDim.x) {
        float v0 = p[i * 3], v1 = p[i * 3 + 1], v2 = p[i * 3 + 2];
        mn0 = fminf(mn0, v0); mx0 = fmaxf(mx0, v0);
        mn1 = fminf(mn1, v1); mx1 = fmaxf(mx1, v1);
        mn2 = fminf(mn2, v2); mx2 = fmaxf(mx2, v2);
    }
    __shared__ float s[6][256];
    s[0][t] = mn0; s[1][t] = mn1; s[2][t] = mn2;
    s[3][t] = mx0; s[4][t] = mx1; s[5][t] = mx2;
    __syncthreads();
    for (int w = 128; w > 0; w >>= 1) {
        if (t < w) {
            #pragma unroll
            for (int c = 0; c < 3; c++) {
                s[c][t]     = fminf(s[c][t],     s[c][t + w]);
                s[c + 3][t] = fmaxf(s[c + 3][t], s[c + 3][t + w]);
            }
        }
        __syncthreads();
    }
    if (t < 6) g_mm[b * 6 + t] = s[t][0];
}

// ---------------- Kernel B: morton + stable bitonic argsort (FROZEN) ----------------
__global__ void k_sort(const float* __restrict__ xyz, float* __restrict__ out, int out_size) {
    extern __shared__ unsigned long long keys[];
    int b = blockIdx.x;
    int t = threadIdx.x;
    float mn0 = g_mm[b * 6 + 0], mn1 = g_mm[b * 6 + 1], mn2 = g_mm[b * 6 + 2];
    float s0 = fmaxf(__fsub_rn(g_mm[b * 6 + 3], mn0), 1e-6f);
    float s1 = fmaxf(__fsub_rn(g_mm[b * 6 + 4], mn1), 1e-6f);
    float s2 = fmaxf(__fsub_rn(g_mm[b * 6 + 5], mn2), 1e-6f);
    float r0 = __fdiv_rn(1.0f, s0);
    float r1 = __fdiv_rn(1.0f, s1);
    float r2 = __fdiv_rn(1.0f, s2);
    const float* p = xyz + (size_t)b * NN * 3;

    for (int i = t; i < NN; i += blockDim.x) {
        float u0 = __fmul_rn(__fsub_rn(p[i * 3],     mn0), r0);
        float u1 = __fmul_rn(__fsub_rn(p[i * 3 + 1], mn1), r1);
        float u2 = __fmul_rn(__fsub_rn(p[i * 3 + 2], mn2), r2);
        int q0 = min(max(__float2int_rn(__fmul_rn(u0, 1023.0f)), 0), 1023);
        int q1 = min(max(__float2int_rn(__fmul_rn(u1, 1023.0f)), 0), 1023);
        int q2 = min(max(__float2int_rn(__fmul_rn(u2, 1023.0f)), 0), 1023);
        int code = part1by2_10(q0) | (part1by2_10(q1) << 1) | (part1by2_10(q2) << 2);
        keys[i] = ((unsigned long long)(unsigned)code << 14) | (unsigned long long)i;
    }
    __syncthreads();

    for (int k = 2; k <= NN; k <<= 1) {
        for (int j = k >> 1; j > 0; j >>= 1) {
            for (int i = t; i < NN; i += blockDim.x) {
                int ixj = i ^ j;
                if (ixj > i) {
                    unsigned long long a = keys[i], c = keys[ixj];
                    bool up = ((i & k) == 0);
                    if ((a > c) == up) { keys[i] = c; keys[ixj] = a; }
                }
            }
            __syncthreads();
        }
    }

    for (int i = t; i < NN; i += blockDim.x) {
        int si = (int)(keys[i] & 16383ULL);
        g_sidx[b * NN + i] = si;
        if (out_size >= TOT_SZ) out[IDX_OFF + b * NN + i] = (float)si;
    }
}

// ---------------- Kernel P: 256*W2 -> fp16 hi/lo transposed + swizzled tiles ----------------
__global__ void k_prep(const float* __restrict__ W2) {
    int idx = blockIdx.x * 256 + threadIdx.x;
    if (idx >= HID * ED) return;
    int k = idx / ED, n = idx - k * ED;
    float w = W2[idx] * W2SCALE;          // exact scale keeps lo in fp16-normal range
    __half hi = __float2half(w);
    __half lo = __float2half(w - __half2float(hi));
    int mc = n >> 7, row = n & 127, kc = k >> 6, col = k & 63;
    uint32_t off = (uint32_t)(row * 128 + col * 2);
    off ^= (off >> 3) & 0x70;
    size_t tile = (size_t)(mc * NKC + kc) * TILE_B;
    *(__half*)(g_w2hi + tile + off) = hi;
    *(__half*)(g_w2lo + tile + off) = lo;
}

// ---------------- Kernel H: layer-1 + gelu -> fp16 swizzled tiles in global ----------------
__global__ void __launch_bounds__(NTH) k_hid(
    const float* __restrict__ xyz,
    const float* __restrict__ W1, const float* __restrict__ b1)
{
    __shared__ float rel[NPT * 3];
    __shared__ float cen[24];
    int t = threadIdx.x;
    int blk = blockIdx.x;                 // 2048
    int b = blk >> 7;
    int chunk = blk & 127;
    int m0 = chunk * NPT;

    if (t < NPT) {
        int si = g_sidx[b * NN + m0 + t];
        const float* pp = xyz + ((size_t)b * NN + si) * 3;
        rel[t * 3 + 0] = pp[0];
        rel[t * 3 + 1] = pp[1];
        rel[t * 3 + 2] = pp[2];
    }
    __syncthreads();
    if (t < 24) {
        int g = t / 3, cc = t - g * 3;
        float sum = 0.f;
        #pragma unroll
        for (int p = 0; p < GS; p++) sum += rel[(g * GS + p) * 3 + cc];
        cen[t] = sum * (1.0f / GS);
    }
    __syncthreads();
    for (int i = t; i < NPT * 3; i += NTH) rel[i] -= cen[(i / (GS * 3)) * 3 + i % 3];
    __syncthreads();

    int p = t & 127;
    float rx = rel[p * 3], ry = rel[p * 3 + 1], rz = rel[p * 3 + 2];
    int kq = t >> 7;
    uint32_t hswz = (uint32_t)((p & 7) << 4);
    uint32_t hrow = (uint32_t)(p * 128);
    char* gbase = g_h + (size_t)blk * (NKC * TILE_B);

    for (int kc = 0; kc < NKC; kc++) {
        #pragma unroll
        for (int i = 0; i < 2; i++) {
            int k  = kq * 16 + i * 8;
            int kk = kc * KCH + k;
            float4 wa0 = *(const float4*)(W1 + kk);
            float4 wa1 = *(const float4*)(W1 + kk + 4);
            float4 wb0 = *(const float4*)(W1 + HID + kk);
            float4 wb1 = *(const float4*)(W1 + HID + kk + 4);
            float4 wc0 = *(const float4*)(W1 + 2 * HID + kk);
            float4 wc1 = *(const float4*)(W1 + 2 * HID + kk + 4);
            float4 bb0 = *(const float4*)(b1 + kk);
            float4 bb1 = *(const float4*)(b1 + kk + 4);
            float h[8];
            h[0] = gelu_exact(fmaf(rx, wa0.x, fmaf(ry, wb0.x, fmaf(rz, wc0.x, bb0.x))));
            h[1] = gelu_exact(fmaf(rx, wa0.y, fmaf(ry, wb0.y, fmaf(rz, wc0.y, bb0.y))));
            h[2] = gelu_exact(fmaf(rx, wa0.z, fmaf(ry, wb0.z, fmaf(rz, wc0.z, bb0.z))));
            h[3] = gelu_exact(fmaf(rx, wa0.w, fmaf(ry, wb0.w, fmaf(rz, wc0.w, bb0.w))));
            h[4] = gelu_exact(fmaf(rx, wa1.x, fmaf(ry, wb1.x, fmaf(rz, wc1.x, bb1.x))));
            h[5] = gelu_exact(fmaf(rx, wa1.y, fmaf(ry, wb1.y, fmaf(rz, wc1.y, bb1.y))));
            h[6] = gelu_exact(fmaf(rx, wa1.z, fmaf(ry, wb1.z, fmaf(rz, wc1.z, bb1.z))));
            h[7] = gelu_exact(fmaf(rx, wa1.w, fmaf(ry, wb1.w, fmaf(rz, wc1.w, bb1.w))));
            uint32_t hw[4];
            #pragma unroll
            for (int j = 0; j < 4; j++)
                hw[j] = pack_h2(__float2half(h[2 * j]), __float2half(h[2 * j + 1]));
            uint32_t off = hrow + (((uint32_t)(k * 2)) ^ hswz);
            *(uint4*)(gbase + (size_t)kc * TILE_B + off) = make_uint4(hw[0], hw[1], hw[2], hw[3]);
        }
    }
}

// ---------------- Kernel C: pure split-fp16 GEMM + epilogue, 16 warps ----------------
__global__ void __launch_bounds__(NTH, 1) k_gemm(
    const float* __restrict__ xyz,
    const float* __restrict__ b2,
    const float* __restrict__ Wc, const float* __restrict__ bc,
    float* __restrict__ out, int out_size)
{
    extern __shared__ char sm[];
    uint32_t smb = smem_u32(sm);
    float* rel = (float*)(sm + SM_REL);
    float* cen = (float*)(sm + SM_CEN);

    int t = threadIdx.x, wid = t >> 5, lane = t & 31;
    int blk = blockIdx.x;                 // 2048
    int b = blk >> 7;
    int chunk = blk & 127;
    int gbase = chunk * 8;
    int m0 = chunk * NPT;
    const char* hgbase = g_h + (size_t)blk * (NKC * TILE_B);

    // gather + centers (for epilogue + output)
    if (t < NPT) {
        int si = g_sidx[b * NN + m0 + t];
        const float* pp = xyz + ((size_t)b * NN + si) * 3;
        rel[t * 3 + 0] = pp[0];
        rel[t * 3 + 1] = pp[1];
        rel[t * 3 + 2] = pp[2];
    }
    __syncthreads();
    if (t < 24) {
        int g = t / 3, cc = t - g * 3;
        float sum = 0.f;
        #pragma unroll
        for (int p = 0; p < GS; p++) sum += rel[(g * GS + p) * 3 + cc];
        float cv = sum * (1.0f / GS);
        cen[t] = cv;
        if (out_size >= CEN_OFF + BB * GG * 3)
            out[CEN_OFF + ((size_t)b * GG + gbase + g) * 3 + cc] = cv;
    }
    __syncthreads();

    // cp.async stage: W2hi | W2lo | H for (mc, kc) into stage bi
    auto cp_issue = [&](int mc, int kc, int bi) {
        size_t wt = (size_t)(mc * NKC + kc) * TILE_B;
        const char* sh = g_w2hi + wt;
        const char* sl = g_w2lo + wt;
        const char* hh = hgbase + (size_t)kc * TILE_B;
        uint32_t d = smb + bi * STAGE_B;
        #pragma unroll
        for (int i = 0; i < 2; i++) {
            uint32_t o = (uint32_t)(t * 16 + i * 8192);
            asm volatile("cp.async.cg.shared.global [%0], [%1], 16;"
                :: "r"(d + o), "l"(__cvta_generic_to_global(sh + o)) : "memory");
            asm volatile("cp.async.cg.shared.global [%0], [%1], 16;"
                :: "r"(d + 16384 + o), "l"(__cvta_generic_to_global(sl + o)) : "memory");
            asm volatile("cp.async.cg.shared.global [%0], [%1], 16;"
                :: "r"(d + 32768 + o), "l"(__cvta_generic_to_global(hh + o)) : "memory");
        }
        asm volatile("cp.async.commit_group;" ::: "memory");
    };

    int m0w = (wid & 3) * 32;      // warp M offset
    int n0w = (wid >> 2) * 32;     // warp N offset

    // base swizzled offsets; off(ks) = base ^ (ks<<5); mf/nfp step = +2048; lo = +16384
    int rowA = m0w + (lane & 15);
    uint32_t baseA = (uint32_t)(rowA * 128) + ((((uint32_t)(lane >> 4)) << 4) ^ ((uint32_t)(rowA & 7) << 4));
    int gq = lane >> 3;
    int rowB = n0w + (gq >> 1) * 8 + (lane & 7);
    uint32_t baseB = (uint32_t)(rowB * 128) + ((((uint32_t)(gq & 1)) << 4) ^ ((uint32_t)(rowB & 7) << 4));

    for (int mc = 0; mc < 3; mc++) {
        float c[2][4][4];
        #pragma unroll
        for (int mf = 0; mf < 2; mf++)
            #pragma unroll
            for (int nf = 0; nf < 4; nf++)
                #pragma unroll
                for (int q = 0; q < 4; q++) c[mf][nf][q] = 0.f;

        cp_issue(mc, 0, 0);
        cp_issue(mc, 1, 1);

        for (int kc = 0; kc < NKC; kc++) {
            int bi = kc & 1;
            if (kc < NKC - 1) { asm volatile("cp.async.wait_group 1;" ::: "memory"); }
            else              { asm volatile("cp.async.wait_group 0;" ::: "memory"); }
            __syncthreads();

            uint32_t sW = smb + bi * STAGE_B;
            uint32_t sH = sW + 32768;
            #pragma unroll
            for (int ks = 0; ks < 4; ks++) {
                uint32_t xk = (uint32_t)(ks << 5);
                uint32_t aA = sW + (baseA ^ xk);
                uint32_t ahi0[4], ahi1[4], alo0[4], alo1[4];
                ldmx4(ahi0, aA);
                ldmx4(ahi1, aA + 2048);
                ldmx4(alo0, aA + 16384);
                ldmx4(alo1, aA + 18432);
                uint32_t aB = sH + (baseB ^ xk);
                uint32_t b0[4], b1r[4];
                ldmx4(b0, aB);
                ldmx4(b1r, aB + 2048);
                // same MMA order as R12: nfp{half{mf{hi,lo}}}
                mma16816h(c[0][0], ahi0, b0);      mma16816h(c[0][0], alo0, b0);
                mma16816h(c[1][0], ahi1, b0);      mma16816h(c[1][0], alo1, b0);
                mma16816h(c[0][1], ahi0, b0 + 2);  mma16816h(c[0][1], alo0, b0 + 2);
                mma16816h(c[1][1], ahi1, b0 + 2);  mma16816h(c[1][1], alo1, b0 + 2);
                mma16816h(c[0][2], ahi0, b1r);     mma16816h(c[0][2], alo0, b1r);
                mma16816h(c[1][2], ahi1, b1r);     mma16816h(c[1][2], alo1, b1r);
                mma16816h(c[0][3], ahi0, b1r + 2); mma16816h(c[0][3], alo0, b1r + 2);
                mma16816h(c[1][3], ahi1, b1r + 2); mma16816h(c[1][3], alo1, b1r + 2);
            }
            __syncthreads();

            if (kc + 2 < NKC) cp_issue(mc, kc + 2, bi);
        }

        // epilogue: unscale + bias + gelu + group max (quad shuffle) + center proj
        #pragma unroll
        for (int mf = 0; mf < 2; mf++) {
            int row0 = mc * 128 + m0w + mf * 16 + (lane >> 2);
            int row1 = row0 + 8;
            float bias0 = b2[row0], bias1 = b2[row1];
            #pragma unroll
            for (int g = 0; g < 2; g++) {
                float va = -1e30f, vb = -1e30f;
                #pragma unroll
                for (int q = 0; q < 2; q++) {
                    float* cc = c[mf][2 * g + q];
                    va = fmaxf(va, fmaxf(gelu_exact(fmaf(cc[0], INVW2SCALE, bias0)),
                                         gelu_exact(fmaf(cc[1], INVW2SCALE, bias0))));
                    vb = fmaxf(vb, fmaxf(gelu_exact(fmaf(cc[2], INVW2SCALE, bias1)),
                                         gelu_exact(fmaf(cc[3], INVW2SCALE, bias1))));
                }
                va = fmaxf(va, __shfl_xor_sync(0xffffffffu, va, 1));
                va = fmaxf(va, __shfl_xor_sync(0xffffffffu, va, 2));
                vb = fmaxf(vb, __shfl_xor_sync(0xffffffffu, vb, 1));
                vb = fmaxf(vb, __shfl_xor_sync(0xffffffffu, vb, 2));
                if ((lane & 3) == 0) {
                    int gl = (wid >> 2) * 2 + g;
                    int gg = gbase + gl;
                    float c0_ = cen[gl * 3], c1_ = cen[gl * 3 + 1], c2_ = cen[gl * 3 + 2];
                    out[TOK_OFF + ((size_t)b * GG + gg) * ED + row0] =
                        va + c0_ * Wc[row0] + c1_ * Wc[ED + row0] + c2_ * Wc[2 * ED + row0] + bc[row0];
                    out[TOK_OFF + ((size_t)b * GG + gg) * ED + row1] =
                        vb + c0_ * Wc[row1] + c1_ * Wc[ED + row1] + c2_ * Wc[2 * ED + row1] + bc[row1];
                }
            }
        }
        __syncthreads();
    }
}

extern "C" void kernel_launch(void* const* d_in, const int* in_sizes, int n_in,
                              void* d_out, int out_size) {
    const float* xyz = (const float*)d_in[0];
    const float* W1  = (const float*)d_in[1];
    const float* b1  = (const float*)d_in[2];
    const float* W2  = (const float*)d_in[3];
    const float* b2  = (const float*)d_in[4];
    const float* Wc  = (const float*)d_in[5];
    const float* bc  = (const float*)d_in[6];
    float* out = (float*)d_out;

    const int sort_smem = NN * 8;
    cudaFuncSetAttribute(k_sort, cudaFuncAttributeMaxDynamicSharedMemorySize, sort_smem);
    cudaFuncSetAttribute(k_gemm, cudaFuncAttributeMaxDynamicSharedMemorySize, SM_TOTAL);

    k_minmax<<<BB, 256>>>(xyz);
    k_sort<<<BB, 1024, sort_smem>>>(xyz, out, out_size);
    k_prep<<<(HID * ED + 255) / 256, 256>>>(W2);
    k_hid<<<2048, NTH>>>(xyz, W1, b1);
    k_gemm<<<2048, NTH, SM_TOTAL>>>(xyz, b2, Wc, bc, out, out_size);
}

// round 14
// speedup vs baseline: 2.9500x; 1.1081x over previous
#include <cuda_runtime.h>
#include <cuda_bf16.h>
#include <cuda_fp16.h>
#include <cstdint>

#define BB   16
#define NN   16384
#define GS   16
#define GG   1024
#define HID  768
#define ED   384

// output layout (floats): tokens | centers | group_idx(as float)
#define TOK_OFF 0
#define CEN_OFF (BB*GG*ED)
#define IDX_OFF (CEN_OFF + BB*GG*3)
#define TOT_SZ  (IDX_OFF + BB*GG*GS)

// GEMM tiling
#define NPT 128                  // points per CTA (8 groups)
#define KCH 64                   // K chunk
#define NKC (HID/KCH)            // 12
#define TILE_B 16384             // one 128x64 fp16 tile
#define NTH 512                  // threads per CTA (16 warps)
#define W2SCALE 256.0f
#define INVW2SCALE (1.0f/256.0f)

// smem: per stage W2hi(16K) | W2lo(16K) | H(16K); two stages
#define STAGE_B 49152
#define SM_REL    98304                   // 384 floats
#define SM_CEN    99840                   // 24 floats
#define SM_TOTAL  99968

// sort chunking
#define SCH 4096                          // chunk elements for smem sort phases

__device__ float g_mm[BB * 6];
__device__ int   g_sidx[BB * NN];
__device__ unsigned long long g_keys[BB * NN];   // 2 MB scratch
__device__ __align__(16) char g_w2hi[3 * NKC * TILE_B];
__device__ __align__(16) char g_w2lo[3 * NKC * TILE_B];
__device__ __align__(16) char g_h[(size_t)2048 * NKC * TILE_B];   // 402 MB H tiles

__device__ __forceinline__ float gelu_exact(float x) {
    return 0.5f * x * (1.0f + erff(x * 0.70710678118654752f));
}
__device__ __forceinline__ int part1by2_10(int v) {
    v &= 1023;
    v = (v | (v << 16)) & 50331903;
    v = (v | (v << 8))  & 50393103;
    v = (v | (v << 4))  & 51130563;
    v = (v | (v << 2))  & 153391689;
    return v;
}
__device__ __forceinline__ uint32_t smem_u32(const void* p) {
    uint32_t a;
    asm("{ .reg .u64 t; cvta.to.shared.u64 t, %1; cvt.u32.u64 %0, t; }" : "=r"(a) : "l"(p));
    return a;
}
__device__ __forceinline__ void ldmx4(uint32_t* r, uint32_t a) {
    asm volatile("ldmatrix.sync.aligned.m8n8.x4.shared.b16 {%0,%1,%2,%3}, [%4];"
        : "=r"(r[0]), "=r"(r[1]), "=r"(r[2]), "=r"(r[3]) : "r"(a));
}
__device__ __forceinline__ void mma16816h(float* c, const uint32_t* a, const uint32_t* b) {
    asm volatile(
        "mma.sync.aligned.m16n8k16.row.col.f32.f16.f16.f32 "
        "{%0,%1,%2,%3}, {%4,%5,%6,%7}, {%8,%9}, {%0,%1,%2,%3};"
        : "+f"(c[0]), "+f"(c[1]), "+f"(c[2]), "+f"(c[3])
        : "r"(a[0]), "r"(a[1]), "r"(a[2]), "r"(a[3]), "r"(b[0]), "r"(b[1]));
}
__device__ __forceinline__ uint32_t pack_h2(__half a, __half b) {
    __half2 h2 = __halves2half2(a, b);
    return *(uint32_t*)&h2;
}

// ---------------- Kernel A: per-batch min/max (FROZEN) ----------------
__global__ void k_minmax(const float* __restrict__ xyz) {
    int b = blockIdx.x;
    int t = threadIdx.x;
    const float* p = xyz + (size_t)b * NN * 3;
    float mn0 = 1e30f, mn1 = 1e30f, mn2 = 1e30f;
    float mx0 = -1e30f, mx1 = -1e30f, mx2 = -1e30f;
    for (int i = t; i < NN; i += blockDim.x) {
        float v0 = p[i * 3], v1 = p[i * 3 + 1], v2 = p[i * 3 + 2];
        mn0 = fminf(mn0, v0); mx0 = fmaxf(mx0, v0);
        mn1 = fminf(mn1, v1); mx1 = fmaxf(mx1, v1);
        mn2 = fminf(mn2, v2); mx2 = fmaxf(mx2, v2);
    }
    __shared__ float s[6][256];
    s[0][t] = mn0; s[1][t] = mn1; s[2][t] = mn2;
    s[3][t] = mx0; s[4][t] = mx1; s[5][t] = mx2;
    __syncthreads();
    for (int w = 128; w > 0; w >>= 1) {
        if (t < w) {
            #pragma unroll
            for (int c = 0; c < 3; c++) {
                s[c][t]     = fminf(s[c][t],     s[c][t + w]);
                s[c + 3][t] = fmaxf(s[c + 3][t], s[c + 3][t + w]);
            }
        }
        __syncthreads();
    }
    if (t < 6) g_mm[b * 6 + t] = s[t][0];
}

// ---------------- Sort phase 1: codes + bitonic k=2..4096 in 4096-chunks ----------------
// Same canonical network as before, distributed. Keys unique -> identical result.
__global__ void __launch_bounds__(1024) k_sort_p1(const float* __restrict__ xyz) {
    __shared__ unsigned long long keys[SCH];
    int blk = blockIdx.x;            // 64 = 16 batches x 4 chunks
    int b = blk >> 2, cidx = blk & 3;
    int base = cidx * SCH;
    int t = threadIdx.x;

    float mn0 = g_mm[b * 6 + 0], mn1 = g_mm[b * 6 + 1], mn2 = g_mm[b * 6 + 2];
    float s0 = fmaxf(__fsub_rn(g_mm[b * 6 + 3], mn0), 1e-6f);
    float s1 = fmaxf(__fsub_rn(g_mm[b * 6 + 4], mn1), 1e-6f);
    float s2 = fmaxf(__fsub_rn(g_mm[b * 6 + 5], mn2), 1e-6f);
    float r0 = __fdiv_rn(1.0f, s0);
    float r1 = __fdiv_rn(1.0f, s1);
    float r2 = __fdiv_rn(1.0f, s2);
    const float* p = xyz + (size_t)b * NN * 3;

    for (int li = t; li < SCH; li += 1024) {
        int i = base + li;
        float u0 = __fmul_rn(__fsub_rn(p[i * 3],     mn0), r0);
        float u1 = __fmul_rn(__fsub_rn(p[i * 3 + 1], mn1), r1);
        float u2 = __fmul_rn(__fsub_rn(p[i * 3 + 2], mn2), r2);
        int q0 = min(max(__float2int_rn(__fmul_rn(u0, 1023.0f)), 0), 1023);
        int q1 = min(max(__float2int_rn(__fmul_rn(u1, 1023.0f)), 0), 1023);
        int q2 = min(max(__float2int_rn(__fmul_rn(u2, 1023.0f)), 0), 1023);
        int code = part1by2_10(q0) | (part1by2_10(q1) << 1) | (part1by2_10(q2) << 2);
        keys[li] = ((unsigned long long)(unsigned)code << 14) | (unsigned long long)i;
    }
    __syncthreads();

    for (int k = 2; k <= SCH; k <<= 1) {
        for (int j = k >> 1; j > 0; j >>= 1) {
            for (int li = t; li < SCH; li += 1024) {
                int lixj = li ^ j;               // j < SCH -> partner in chunk
                if (lixj > li) {
                    unsigned long long a = keys[li], c = keys[lixj];
                    bool up = (((base + li) & k) == 0);   // direction from GLOBAL index
                    if ((a > c) == up) { keys[li] = c; keys[lixj] = a; }
                }
            }
            __syncthreads();
        }
    }

    for (int li = t; li < SCH; li += 1024)
        g_keys[b * NN + base + li] = keys[li];
}

// ---------------- Sort: one cross-chunk j-step in global memory ----------------
__global__ void k_sort_gpass(int k, int j) {
    int pidx = blockIdx.x * 256 + threadIdx.x;      // 131072 pairs total
    int b = pidx >> 13, pin = pidx & 8191;
    int i = ((pin & ~(j - 1)) << 1) | (pin & (j - 1));
    int ixj = i | j;
    unsigned long long* kb = g_keys + (size_t)b * NN;
    unsigned long long a = kb[i], c = kb[ixj];
    bool up = ((i & k) == 0);
    if ((a > c) == up) { kb[i] = c; kb[ixj] = a; }
}

// ---------------- Sort phase 2: j=2048..1 of level k in 4096-chunks ----------------
__global__ void __launch_bounds__(1024) k_sort_p2(int k, int final_lvl,
                                                  float* __restrict__ out, int out_size) {
    __shared__ unsigned long long keys[SCH];
    int blk = blockIdx.x;
    int b = blk >> 2, cidx = blk & 3;
    int base = cidx * SCH;
    int t = threadIdx.x;

    for (int li = t; li < SCH; li += 1024) keys[li] = g_keys[b * NN + base + li];
    __syncthreads();

    for (int j = 2048; j > 0; j >>= 1) {
        for (int li = t; li < SCH; li += 1024) {
            int lixj = li ^ j;
            if (lixj > li) {
                unsigned long long a = keys[li], c = keys[lixj];
                bool up = (((base + li) & k) == 0);
                if ((a > c) == up) { keys[li] = c; keys[lixj] = a; }
            }
        }
        __syncthreads();
    }

    if (final_lvl) {
        for (int li = t; li < SCH; li += 1024) {
            int i = base + li;
            int si = (int)(keys[li] & 16383ULL);
            g_sidx[b * NN + i] = si;
            if (out_size >= TOT_SZ) out[IDX_OFF + b * NN + i] = (float)si;
        }
    } else {
        for (int li = t; li < SCH; li += 1024)
            g_keys[b * NN + base + li] = keys[li];
    }
}

// ---------------- Kernel P: 256*W2 -> fp16 hi/lo transposed + swizzled tiles ----------------
__global__ void k_prep(const float* __restrict__ W2) {
    int idx = blockIdx.x * 256 + threadIdx.x;
    if (idx >= HID * ED) return;
    int k = idx / ED, n = idx - k * ED;
    float w = W2[idx] * W2SCALE;          // exact scale keeps lo in fp16-normal range
    __half hi = __float2half(w);
    __half lo = __float2half(w - __half2float(hi));
    int mc = n >> 7, row = n & 127, kc = k >> 6, col = k & 63;
    uint32_t off = (uint32_t)(row * 128 + col * 2);
    off ^= (off >> 3) & 0x70;
    size_t tile = (size_t)(mc * NKC + kc) * TILE_B;
    *(__half*)(g_w2hi + tile + off) = hi;
    *(__half*)(g_w2lo + tile + off) = lo;
}

// ---------------- Kernel H: layer-1 + gelu -> fp16 swizzled tiles in global ----------------
__global__ void __launch_bounds__(NTH) k_hid(
    const float* __restrict__ xyz,
    const float* __restrict__ W1, const float* __restrict__ b1)
{
    __shared__ float rel[NPT * 3];
    __shared__ float cen[24];
    int t = threadIdx.x;
    int blk = blockIdx.x;                 // 2048
    int b = blk >> 7;
    int chunk = blk & 127;
    int m0 = chunk * NPT;

    if (t < NPT) {
        int si = g_sidx[b * NN + m0 + t];
        const float* pp = xyz + ((size_t)b * NN + si) * 3;
        rel[t * 3 + 0] = pp[0];
        rel[t * 3 + 1] = pp[1];
        rel[t * 3 + 2] = pp[2];
    }
    __syncthreads();
    if (t < 24) {
        int g = t / 3, cc = t - g * 3;
        float sum = 0.f;
        #pragma unroll
        for (int p = 0; p < GS; p++) sum += rel[(g * GS + p) * 3 + cc];
        cen[t] = sum * (1.0f / GS);
    }
    __syncthreads();
    for (int i = t; i < NPT * 3; i += NTH) rel[i] -= cen[(i / (GS * 3)) * 3 + i % 3];
    __syncthreads();

    int p = t & 127;
    float rx = rel[p * 3], ry = rel[p * 3 + 1], rz = rel[p * 3 + 2];
    int kq = t >> 7;
    uint32_t hswz = (uint32_t)((p & 7) << 4);
    uint32_t hrow = (uint32_t)(p * 128);
    char* gbase = g_h + (size_t)blk * (NKC * TILE_B);

    for (int kc = 0; kc < NKC; kc++) {
        #pragma unroll
        for (int i = 0; i < 2; i++) {
            int k  = kq * 16 + i * 8;
            int kk = kc * KCH + k;
            float4 wa0 = *(const float4*)(W1 + kk);
            float4 wa1 = *(const float4*)(W1 + kk + 4);
            float4 wb0 = *(const float4*)(W1 + HID + kk);
            float4 wb1 = *(const float4*)(W1 + HID + kk + 4);
            float4 wc0 = *(const float4*)(W1 + 2 * HID + kk);
            float4 wc1 = *(const float4*)(W1 + 2 * HID + kk + 4);
            float4 bb0 = *(const float4*)(b1 + kk);
            float4 bb1 = *(const float4*)(b1 + kk + 4);
            float h[8];
            h[0] = gelu_exact(fmaf(rx, wa0.x, fmaf(ry, wb0.x, fmaf(rz, wc0.x, bb0.x))));
            h[1] = gelu_exact(fmaf(rx, wa0.y, fmaf(ry, wb0.y, fmaf(rz, wc0.y, bb0.y))));
            h[2] = gelu_exact(fmaf(rx, wa0.z, fmaf(ry, wb0.z, fmaf(rz, wc0.z, bb0.z))));
            h[3] = gelu_exact(fmaf(rx, wa0.w, fmaf(ry, wb0.w, fmaf(rz, wc0.w, bb0.w))));
            h[4] = gelu_exact(fmaf(rx, wa1.x, fmaf(ry, wb1.x, fmaf(rz, wc1.x, bb1.x))));
            h[5] = gelu_exact(fmaf(rx, wa1.y, fmaf(ry, wb1.y, fmaf(rz, wc1.y, bb1.y))));
            h[6] = gelu_exact(fmaf(rx, wa1.z, fmaf(ry, wb1.z, fmaf(rz, wc1.z, bb1.z))));
            h[7] = gelu_exact(fmaf(rx, wa1.w, fmaf(ry, wb1.w, fmaf(rz, wc1.w, bb1.w))));
            uint32_t hw[4];
            #pragma unroll
            for (int j = 0; j < 4; j++)
                hw[j] = pack_h2(__float2half(h[2 * j]), __float2half(h[2 * j + 1]));
            uint32_t off = hrow + (((uint32_t)(k * 2)) ^ hswz);
            *(uint4*)(gbase + (size_t)kc * TILE_B + off) = make_uint4(hw[0], hw[1], hw[2], hw[3]);
        }
    }
}

// ---------------- Kernel C: pure split-fp16 GEMM + epilogue, 16 warps ----------------
__global__ void __launch_bounds__(NTH, 1) k_gemm(
    const float* __restrict__ xyz,
    const float* __restrict__ b2,
    const float* __restrict__ Wc, const float* __restrict__ bc,
    float* __restrict__ out, int out_size)
{
    extern __shared__ char sm[];
    uint32_t smb = smem_u32(sm);
    float* rel = (float*)(sm + SM_REL);
    float* cen = (float*)(sm + SM_CEN);

    int t = threadIdx.x, wid = t >> 5, lane = t & 31;
    int blk = blockIdx.x;                 // 2048
    int b = blk >> 7;
    int chunk = blk & 127;
    int gbase = chunk * 8;
    int m0 = chunk * NPT;
    const char* hgbase = g_h + (size_t)blk * (NKC * TILE_B);

    // gather + centers (for epilogue + output)
    if (t < NPT) {
        int si = g_sidx[b * NN + m0 + t];
        const float* pp = xyz + ((size_t)b * NN + si) * 3;
        rel[t * 3 + 0] = pp[0];
        rel[t * 3 + 1] = pp[1];
        rel[t * 3 + 2] = pp[2];
    }
    __syncthreads();
    if (t < 24) {
        int g = t / 3, cc = t - g * 3;
        float sum = 0.f;
        #pragma unroll
        for (int p = 0; p < GS; p++) sum += rel[(g * GS + p) * 3 + cc];
        float cv = sum * (1.0f / GS);
        cen[t] = cv;
        if (out_size >= CEN_OFF + BB * GG * 3)
            out[CEN_OFF + ((size_t)b * GG + gbase + g) * 3 + cc] = cv;
    }
    __syncthreads();

    // cp.async stage: W2hi | W2lo | H for (mc, kc) into stage bi
    auto cp_issue = [&](int mc, int kc, int bi) {
        size_t wt = (size_t)(mc * NKC + kc) * TILE_B;
        const char* sh = g_w2hi + wt;
        const char* sl = g_w2lo + wt;
        const char* hh = hgbase + (size_t)kc * TILE_B;
        uint32_t d = smb + bi * STAGE_B;
        #pragma unroll
        for (int i = 0; i < 2; i++) {
            uint32_t o = (uint32_t)(t * 16 + i * 8192);
            asm volatile("cp.async.cg.shared.global [%0], [%1], 16;"
                :: "r"(d + o), "l"(__cvta_generic_to_global(sh + o)) : "memory");
            asm volatile("cp.async.cg.shared.global [%0], [%1], 16;"
                :: "r"(d + 16384 + o), "l"(__cvta_generic_to_global(sl + o)) : "memory");
            asm volatile("cp.async.cg.shared.global [%0], [%1], 16;"
                :: "r"(d + 32768 + o), "l"(__cvta_generic_to_global(hh + o)) : "memory");
        }
        asm volatile("cp.async.commit_group;" ::: "memory");
    };

    int m0w = (wid & 3) * 32;      // warp M offset
    int n0w = (wid >> 2) * 32;     // warp N offset

    // base swizzled offsets; off(ks) = base ^ (ks<<5); mf/nfp step = +2048; lo = +16384
    int rowA = m0w + (lane & 15);
    uint32_t baseA = (uint32_t)(rowA * 128) + ((((uint32_t)(lane >> 4)) << 4) ^ ((uint32_t)(rowA & 7) << 4));
    int gq = lane >> 3;
    int rowB = n0w + (gq >> 1) * 8 + (lane & 7);
    uint32_t baseB = (uint32_t)(rowB * 128) + ((((uint32_t)(gq & 1)) << 4) ^ ((uint32_t)(rowB & 7) << 4));

    for (int mc = 0; mc < 3; mc++) {
        float c[2][4][4];
        #pragma unroll
        for (int mf = 0; mf < 2; mf++)
            #pragma unroll
            for (int nf = 0; nf < 4; nf++)
                #pragma unroll
                for (int q = 0; q < 4; q++) c[mf][nf][q] = 0.f;

        cp_issue(mc, 0, 0);
        cp_issue(mc, 1, 1);

        for (int kc = 0; kc < NKC; kc++) {
            int bi = kc & 1;
            if (kc < NKC - 1) { asm volatile("cp.async.wait_group 1;" ::: "memory"); }
            else              { asm volatile("cp.async.wait_group 0;" ::: "memory"); }
            __syncthreads();

            uint32_t sW = smb + bi * STAGE_B;
            uint32_t sH = sW + 32768;
            #pragma unroll
            for (int ks = 0; ks < 4; ks++) {
                uint32_t xk = (uint32_t)(ks << 5);
                uint32_t aA = sW + (baseA ^ xk);
                uint32_t ahi0[4], ahi1[4], alo0[4], alo1[4];
                ldmx4(ahi0, aA);
                ldmx4(ahi1, aA + 2048);
                ldmx4(alo0, aA + 16384);
                ldmx4(alo1, aA + 18432);
                uint32_t aB = sH + (baseB ^ xk);
                uint32_t b0[4], b1r[4];
                ldmx4(b0, aB);
                ldmx4(b1r, aB + 2048);
                mma16816h(c[0][0], ahi0, b0);      mma16816h(c[0][0], alo0, b0);
                mma16816h(c[1][0], ahi1, b0);      mma16816h(c[1][0], alo1, b0);
                mma16816h(c[0][1], ahi0, b0 + 2);  mma16816h(c[0][1], alo0, b0 + 2);
                mma16816h(c[1][1], ahi1, b0 + 2);  mma16816h(c[1][1], alo1, b0 + 2);
                mma16816h(c[0][2], ahi0, b1r);     mma16816h(c[0][2], alo0, b1r);
                mma16816h(c[1][2], ahi1, b1r);     mma16816h(c[1][2], alo1, b1r);
                mma16816h(c[0][3], ahi0, b1r + 2); mma16816h(c[0][3], alo0, b1r + 2);
                mma16816h(c[1][3], ahi1, b1r + 2); mma16816h(c[1][3], alo1, b1r + 2);
            }
            __syncthreads();

            if (kc + 2 < NKC) cp_issue(mc, kc + 2, bi);
        }

        // epilogue: unscale + bias + gelu + group max (quad shuffle) + center proj
        #pragma unroll
        for (int mf = 0; mf < 2; mf++) {
            int row0 = mc * 128 + m0w + mf * 16 + (lane >> 2);
            int row1 = row0 + 8;
            float bias0 = b2[row0], bias1 = b2[row1];
            #pragma unroll
            for (int g = 0; g < 2; g++) {
                float va = -1e30f, vb = -1e30f;
                #pragma unroll
                for (int q = 0; q < 2; q++) {
                    float* cc = c[mf][2 * g + q];
                    va = fmaxf(va, fmaxf(gelu_exact(fmaf(cc[0], INVW2SCALE, bias0)),
                                         gelu_exact(fmaf(cc[1], INVW2SCALE, bias0))));
                    vb = fmaxf(vb, fmaxf(gelu_exact(fmaf(cc[2], INVW2SCALE, bias1)),
                                         gelu_exact(fmaf(cc[3], INVW2SCALE, bias1))));
                }
                va = fmaxf(va, __shfl_xor_sync(0xffffffffu, va, 1));
                va = fmaxf(va, __shfl_xor_sync(0xffffffffu, va, 2));
                vb = fmaxf(vb, __shfl_xor_sync(0xffffffffu, vb, 1));
                vb = fmaxf(vb, __shfl_xor_sync(0xffffffffu, vb, 2));
                if ((lane & 3) == 0) {
                    int gl = (wid >> 2) * 2 + g;
                    int gg = gbase + gl;
                    float c0_ = cen[gl * 3], c1_ = cen[gl * 3 + 1], c2_ = cen[gl * 3 + 2];
                    out[TOK_OFF + ((size_t)b * GG + gg) * ED + row0] =
                        va + c0_ * Wc[row0] + c1_ * Wc[ED + row0] + c2_ * Wc[2 * ED + row0] + bc[row0];
                    out[TOK_OFF + ((size_t)b * GG + gg) * ED + row1] =
                        vb + c0_ * Wc[row1] + c1_ * Wc[ED + row1] + c2_ * Wc[2 * ED + row1] + bc[row1];
                }
            }
        }
        __syncthreads();
    }
}

extern "C" void kernel_launch(void* const* d_in, const int* in_sizes, int n_in,
                              void* d_out, int out_size) {
    const float* xyz = (const float*)d_in[0];
    const float* W1  = (const float*)d_in[1];
    const float* b1  = (const float*)d_in[2];
    const float* W2  = (const float*)d_in[3];
    const float* b2  = (const float*)d_in[4];
    const float* Wc  = (const float*)d_in[5];
    const float* bc  = (const float*)d_in[6];
    float* out = (float*)d_out;

    cudaFuncSetAttribute(k_gemm, cudaFuncAttributeMaxDynamicSharedMemorySize, SM_TOTAL);

    k_minmax<<<BB, 256>>>(xyz);
    // distributed canonical bitonic sort (keys unique -> same permutation)
    k_sort_p1<<<BB * (NN / SCH), 1024>>>(xyz);
    k_sort_gpass<<<BB * NN / 2 / 256, 256>>>(8192, 4096);
    k_sort_p2<<<BB * (NN / SCH), 1024>>>(8192, 0, out, out_size);
    k_sort_gpass<<<BB * NN / 2 / 256, 256>>>(16384, 8192);
    k_sort_gpass<<<BB * NN / 2 / 256, 256>>>(16384, 4096);
    k_sort_p2<<<BB * (NN / SCH), 1024>>>(16384, 1, out, out_size);

    k_prep<<<(HID * ED + 255) / 256, 256>>>(W2);
    k_hid<<<2048, NTH>>>(xyz, W1, b1);
    k_gemm<<<2048, NTH, SM_TOTAL>>>(xyz, b2, Wc, bc, out, out_size);
}

// round 15
// speedup vs baseline: 4.2396x; 1.4371x over previous
#include <cuda_runtime.h>
#include <cuda_bf16.h>
#include <cuda_fp16.h>
#include <cstdint>

#define BB   16
#define NN   16384
#define GS   16
#define GG   1024
#define HID  768
#define ED   384

// output layout (floats): tokens | centers | group_idx(as float)
#define TOK_OFF 0
#define CEN_OFF (BB*GG*ED)
#define IDX_OFF (CEN_OFF + BB*GG*3)
#define TOT_SZ  (IDX_OFF + BB*GG*GS)

// GEMM tiling
#define NPT 128                  // points per CTA (8 groups)
#define KCH 64                   // K chunk
#define NKC (HID/KCH)            // 12
#define TILE_B 16384             // one 128x64 fp16 tile
#define NTH 512                  // threads per CTA (16 warps)
#define W2SCALE 256.0f
#define INVW2SCALE (1.0f/256.0f)

// smem: per stage W2(16K) | H(16K); two stages
#define STAGE_B 32768
#define SM_REL    65536                   // 384 floats
#define SM_CEN    67072                   // 24 floats
#define SM_TOTAL  67200

// sort chunking
#define SCH 4096

__device__ float g_mm[BB * 6];
__device__ int   g_sidx[BB * NN];
__device__ unsigned long long g_keys[BB * NN];
__device__ __align__(16) char g_w2hi[3 * NKC * TILE_B];
__device__ __align__(16) char g_h[(size_t)2048 * NKC * TILE_B];   // 402 MB H tiles

__device__ __forceinline__ float gelu_exact(float x) {
    return 0.5f * x * (1.0f + erff(x * 0.70710678118654752f));
}
// tanh-form GELU with HW tanh.approx (used only for H, which is fp16-quantized after)
__device__ __forceinline__ float gelu_fast(float x) {
    float inner = 0.7978845608028654f * fmaf(0.044715f * x, x * x, x);
    float t;
    asm("tanh.approx.f32 %0, %1;" : "=f"(t) : "f"(inner));
    return 0.5f * x * (1.0f + t);
}
__device__ __forceinline__ int part1by2_10(int v) {
    v &= 1023;
    v = (v | (v << 16)) & 50331903;
    v = (v | (v << 8))  & 50393103;
    v = (v | (v << 4))  & 51130563;
    v = (v | (v << 2))  & 153391689;
    return v;
}
__device__ __forceinline__ uint32_t smem_u32(const void* p) {
    uint32_t a;
    asm("{ .reg .u64 t; cvta.to.shared.u64 t, %1; cvt.u32.u64 %0, t; }" : "=r"(a) : "l"(p));
    return a;
}
__device__ __forceinline__ void ldmx4(uint32_t* r, uint32_t a) {
    asm volatile("ldmatrix.sync.aligned.m8n8.x4.shared.b16 {%0,%1,%2,%3}, [%4];"
        : "=r"(r[0]), "=r"(r[1]), "=r"(r[2]), "=r"(r[3]) : "r"(a));
}
__device__ __forceinline__ void mma16816h(float* c, const uint32_t* a, const uint32_t* b) {
    asm volatile(
        "mma.sync.aligned.m16n8k16.row.col.f32.f16.f16.f32 "
        "{%0,%1,%2,%3}, {%4,%5,%6,%7}, {%8,%9}, {%0,%1,%2,%3};"
        : "+f"(c[0]), "+f"(c[1]), "+f"(c[2]), "+f"(c[3])
        : "r"(a[0]), "r"(a[1]), "r"(a[2]), "r"(a[3]), "r"(b[0]), "r"(b[1]));
}
__device__ __forceinline__ uint32_t pack_h2(__half a, __half b) {
    __half2 h2 = __halves2half2(a, b);
    return *(uint32_t*)&h2;
}

// ---------------- Kernel A: per-batch min/max (FROZEN) ----------------
__global__ void k_minmax(const float* __restrict__ xyz) {
    int b = blockIdx.x;
    int t = threadIdx.x;
    const float* p = xyz + (size_t)b * NN * 3;
    float mn0 = 1e30f, mn1 = 1e30f, mn2 = 1e30f;
    float mx0 = -1e30f, mx1 = -1e30f, mx2 = -1e30f;
    for (int i = t; i < NN; i += blockDim.x) {
        float v0 = p[i * 3], v1 = p[i * 3 + 1], v2 = p[i * 3 + 2];
        mn0 = fminf(mn0, v0); mx0 = fmaxf(mx0, v0);
        mn1 = fminf(mn1, v1); mx1 = fmaxf(mx1, v1);
        mn2 = fminf(mn2, v2); mx2 = fmaxf(mx2, v2);
    }
    __shared__ float s[6][256];
    s[0][t] = mn0; s[1][t] = mn1; s[2][t] = mn2;
    s[3][t] = mx0; s[4][t] = mx1; s[5][t] = mx2;
    __syncthreads();
    for (int w = 128; w > 0; w >>= 1) {
        if (t < w) {
            #pragma unroll
            for (int c = 0; c < 3; c++) {
                s[c][t]     = fminf(s[c][t],     s[c][t + w]);
                s[c + 3][t] = fmaxf(s[c + 3][t], s[c + 3][t + w]);
            }
        }
        __syncthreads();
    }
    if (t < 6) g_mm[b * 6 + t] = s[t][0];
}

// ---------------- Sort phase 1: codes + bitonic k=2..4096 (FROZEN network) ----------------
__global__ void __launch_bounds__(1024) k_sort_p1(const float* __restrict__ xyz) {
    __shared__ unsigned long long keys[SCH];
    int blk = blockIdx.x;
    int b = blk >> 2, cidx = blk & 3;
    int base = cidx * SCH;
    int t = threadIdx.x;

    float mn0 = g_mm[b * 6 + 0], mn1 = g_mm[b * 6 + 1], mn2 = g_mm[b * 6 + 2];
    float s0 = fmaxf(__fsub_rn(g_mm[b * 6 + 3], mn0), 1e-6f);
    float s1 = fmaxf(__fsub_rn(g_mm[b * 6 + 4], mn1), 1e-6f);
    float s2 = fmaxf(__fsub_rn(g_mm[b * 6 + 5], mn2), 1e-6f);
    float r0 = __fdiv_rn(1.0f, s0);
    float r1 = __fdiv_rn(1.0f, s1);
    float r2 = __fdiv_rn(1.0f, s2);
    const float* p = xyz + (size_t)b * NN * 3;

    for (int li = t; li < SCH; li += 1024) {
        int i = base + li;
        float u0 = __fmul_rn(__fsub_rn(p[i * 3],     mn0), r0);
        float u1 = __fmul_rn(__fsub_rn(p[i * 3 + 1], mn1), r1);
        float u2 = __fmul_rn(__fsub_rn(p[i * 3 + 2], mn2), r2);
        int q0 = min(max(__float2int_rn(__fmul_rn(u0, 1023.0f)), 0), 1023);
        int q1 = min(max(__float2int_rn(__fmul_rn(u1, 1023.0f)), 0), 1023);
        int q2 = min(max(__float2int_rn(__fmul_rn(u2, 1023.0f)), 0), 1023);
        int code = part1by2_10(q0) | (part1by2_10(q1) << 1) | (part1by2_10(q2) << 2);
        keys[li] = ((unsigned long long)(unsigned)code << 14) | (unsigned long long)i;
    }
    __syncthreads();

    for (int k = 2; k <= SCH; k <<= 1) {
        for (int j = k >> 1; j > 0; j >>= 1) {
            for (int li = t; li < SCH; li += 1024) {
                int lixj = li ^ j;
                if (lixj > li) {
                    unsigned long long a = keys[li], c = keys[lixj];
                    bool up = (((base + li) & k) == 0);
                    if ((a > c) == up) { keys[li] = c; keys[lixj] = a; }
                }
            }
            __syncthreads();
        }
    }

    for (int li = t; li < SCH; li += 1024)
        g_keys[b * NN + base + li] = keys[li];
}

__global__ void k_sort_gpass(int k, int j) {
    int pidx = blockIdx.x * 256 + threadIdx.x;
    int b = pidx >> 13, pin = pidx & 8191;
    int i = ((pin & ~(j - 1)) << 1) | (pin & (j - 1));
    int ixj = i | j;
    unsigned long long* kb = g_keys + (size_t)b * NN;
    unsigned long long a = kb[i], c = kb[ixj];
    bool up = ((i & k) == 0);
    if ((a > c) == up) { kb[i] = c; kb[ixj] = a; }
}

__global__ void __launch_bounds__(1024) k_sort_p2(int k, int final_lvl,
                                                  float* __restrict__ out, int out_size) {
    __shared__ unsigned long long keys[SCH];
    int blk = blockIdx.x;
    int b = blk >> 2, cidx = blk & 3;
    int base = cidx * SCH;
    int t = threadIdx.x;

    for (int li = t; li < SCH; li += 1024) keys[li] = g_keys[b * NN + base + li];
    __syncthreads();

    for (int j = 2048; j > 0; j >>= 1) {
        for (int li = t; li < SCH; li += 1024) {
            int lixj = li ^ j;
            if (lixj > li) {
                unsigned long long a = keys[li], c = keys[lixj];
                bool up = (((base + li) & k) == 0);
                if ((a > c) == up) { keys[li] = c; keys[lixj] = a; }
            }
        }
        __syncthreads();
    }

    if (final_lvl) {
        for (int li = t; li < SCH; li += 1024) {
            int i = base + li;
            int si = (int)(keys[li] & 16383ULL);
            g_sidx[b * NN + i] = si;
            if (out_size >= TOT_SZ) out[IDX_OFF + b * NN + i] = (float)si;
        }
    } else {
        for (int li = t; li < SCH; li += 1024)
            g_keys[b * NN + base + li] = keys[li];
    }
}

// ---------------- Kernel P: 256*W2 -> single fp16 transposed + swizzled tiles ----------------
__global__ void k_prep(const float* __restrict__ W2) {
    int idx = blockIdx.x * 256 + threadIdx.x;
    if (idx >= HID * ED) return;
    int k = idx / ED, n = idx - k * ED;
    __half hi = __float2half(W2[idx] * W2SCALE);   // exact power-of-2 scale
    int mc = n >> 7, row = n & 127, kc = k >> 6, col = k & 63;
    uint32_t off = (uint32_t)(row * 128 + col * 2);
    off ^= (off >> 3) & 0x70;
    size_t tile = (size_t)(mc * NKC + kc) * TILE_B;
    *(__half*)(g_w2hi + tile + off) = hi;
}

// ---------------- Kernel H: layer-1 + fast gelu -> fp16 swizzled tiles ----------------
__global__ void __launch_bounds__(NTH) k_hid(
    const float* __restrict__ xyz,
    const float* __restrict__ W1, const float* __restrict__ b1)
{
    __shared__ float rel[NPT * 3];
    __shared__ float cen[24];
    int t = threadIdx.x;
    int blk = blockIdx.x;
    int b = blk >> 7;
    int chunk = blk & 127;
    int m0 = chunk * NPT;

    if (t < NPT) {
        int si = g_sidx[b * NN + m0 + t];
        const float* pp = xyz + ((size_t)b * NN + si) * 3;
        rel[t * 3 + 0] = pp[0];
        rel[t * 3 + 1] = pp[1];
        rel[t * 3 + 2] = pp[2];
    }
    __syncthreads();
    if (t < 24) {
        int g = t / 3, cc = t - g * 3;
        float sum = 0.f;
        #pragma unroll
        for (int p = 0; p < GS; p++) sum += rel[(g * GS + p) * 3 + cc];
        cen[t] = sum * (1.0f / GS);
    }
    __syncthreads();
    for (int i = t; i < NPT * 3; i += NTH) rel[i] -= cen[(i / (GS * 3)) * 3 + i % 3];
    __syncthreads();

    int p = t & 127;
    float rx = rel[p * 3], ry = rel[p * 3 + 1], rz = rel[p * 3 + 2];
    int kq = t >> 7;
    uint32_t hswz = (uint32_t)((p & 7) << 4);
    uint32_t hrow = (uint32_t)(p * 128);
    char* gbase = g_h + (size_t)blk * (NKC * TILE_B);

    for (int kc = 0; kc < NKC; kc++) {
        #pragma unroll
        for (int i = 0; i < 2; i++) {
            int k  = kq * 16 + i * 8;
            int kk = kc * KCH + k;
            float4 wa0 = *(const float4*)(W1 + kk);
            float4 wa1 = *(const float4*)(W1 + kk + 4);
            float4 wb0 = *(const float4*)(W1 + HID + kk);
            float4 wb1 = *(const float4*)(W1 + HID + kk + 4);
            float4 wc0 = *(const float4*)(W1 + 2 * HID + kk);
            float4 wc1 = *(const float4*)(W1 + 2 * HID + kk + 4);
            float4 bb0 = *(const float4*)(b1 + kk);
            float4 bb1 = *(const float4*)(b1 + kk + 4);
            float h[8];
            h[0] = gelu_fast(fmaf(rx, wa0.x, fmaf(ry, wb0.x, fmaf(rz, wc0.x, bb0.x))));
            h[1] = gelu_fast(fmaf(rx, wa0.y, fmaf(ry, wb0.y, fmaf(rz, wc0.y, bb0.y))));
            h[2] = gelu_fast(fmaf(rx, wa0.z, fmaf(ry, wb0.z, fmaf(rz, wc0.z, bb0.z))));
            h[3] = gelu_fast(fmaf(rx, wa0.w, fmaf(ry, wb0.w, fmaf(rz, wc0.w, bb0.w))));
            h[4] = gelu_fast(fmaf(rx, wa1.x, fmaf(ry, wb1.x, fmaf(rz, wc1.x, bb1.x))));
            h[5] = gelu_fast(fmaf(rx, wa1.y, fmaf(ry, wb1.y, fmaf(rz, wc1.y, bb1.y))));
            h[6] = gelu_fast(fmaf(rx, wa1.z, fmaf(ry, wb1.z, fmaf(rz, wc1.z, bb1.z))));
            h[7] = gelu_fast(fmaf(rx, wa1.w, fmaf(ry, wb1.w, fmaf(rz, wc1.w, bb1.w))));
            uint32_t hw[4];
            #pragma unroll
            for (int j = 0; j < 4; j++)
                hw[j] = pack_h2(__float2half(h[2 * j]), __float2half(h[2 * j + 1]));
            uint32_t off = hrow + (((uint32_t)(k * 2)) ^ hswz);
            *(uint4*)(gbase + (size_t)kc * TILE_B + off) = make_uint4(hw[0], hw[1], hw[2], hw[3]);
        }
    }
}

// ---------------- Kernel C: single-fp16 GEMM + epilogue, 16 warps ----------------
__global__ void __launch_bounds__(NTH, 1) k_gemm(
    const float* __restrict__ xyz,
    const float* __restrict__ b2,
    const float* __restrict__ Wc, const float* __restrict__ bc,
    float* __restrict__ out, int out_size)
{
    extern __shared__ char sm[];
    uint32_t smb = smem_u32(sm);
    float* rel = (float*)(sm + SM_REL);
    float* cen = (float*)(sm + SM_CEN);

    int t = threadIdx.x, wid = t >> 5, lane = t & 31;
    int blk = blockIdx.x;
    int b = blk >> 7;
    int chunk = blk & 127;
    int gbase = chunk * 8;
    int m0 = chunk * NPT;
    const char* hgbase = g_h + (size_t)blk * (NKC * TILE_B);

    if (t < NPT) {
        int si = g_sidx[b * NN + m0 + t];
        const float* pp = xyz + ((size_t)b * NN + si) * 3;
        rel[t * 3 + 0] = pp[0];
        rel[t * 3 + 1] = pp[1];
        rel[t * 3 + 2] = pp[2];
    }
    __syncthreads();
    if (t < 24) {
        int g = t / 3, cc = t - g * 3;
        float sum = 0.f;
        #pragma unroll
        for (int p = 0; p < GS; p++) sum += rel[(g * GS + p) * 3 + cc];
        float cv = sum * (1.0f / GS);
        cen[t] = cv;
        if (out_size >= CEN_OFF + BB * GG * 3)
            out[CEN_OFF + ((size_t)b * GG + gbase + g) * 3 + cc] = cv;
    }
    __syncthreads();

    // cp.async stage: W2 | H for (mc, kc) into stage bi
    auto cp_issue = [&](int mc, int kc, int bi) {
        size_t wt = (size_t)(mc * NKC + kc) * TILE_B;
        const char* sh = g_w2hi + wt;
        const char* hh = hgbase + (size_t)kc * TILE_B;
        uint32_t d = smb + bi * STAGE_B;
        #pragma unroll
        for (int i = 0; i < 2; i++) {
            uint32_t o = (uint32_t)(t * 16 + i * 8192);
            asm volatile("cp.async.cg.shared.global [%0], [%1], 16;"
                :: "r"(d + o), "l"(__cvta_generic_to_global(sh + o)) : "memory");
            asm volatile("cp.async.cg.shared.global [%0], [%1], 16;"
                :: "r"(d + 16384 + o), "l"(__cvta_generic_to_global(hh + o)) : "memory");
        }
        asm volatile("cp.async.commit_group;" ::: "memory");
    };

    int m0w = (wid & 3) * 32;
    int n0w = (wid >> 2) * 32;

    int rowA = m0w + (lane & 15);
    uint32_t baseA = (uint32_t)(rowA * 128) + ((((uint32_t)(lane >> 4)) << 4) ^ ((uint32_t)(rowA & 7) << 4));
    int gq = lane >> 3;
    int rowB = n0w + (gq >> 1) * 8 + (lane & 7);
    uint32_t baseB = (uint32_t)(rowB * 128) + ((((uint32_t)(gq & 1)) << 4) ^ ((uint32_t)(rowB & 7) << 4));

    for (int mc = 0; mc < 3; mc++) {
        float c[2][4][4];
        #pragma unroll
        for (int mf = 0; mf < 2; mf++)
            #pragma unroll
            for (int nf = 0; nf < 4; nf++)
                #pragma unroll
                for (int q = 0; q < 4; q++) c[mf][nf][q] = 0.f;

        cp_issue(mc, 0, 0);
        cp_issue(mc, 1, 1);

        for (int kc = 0; kc < NKC; kc++) {
            int bi = kc & 1;
            if (kc < NKC - 1) { asm volatile("cp.async.wait_group 1;" ::: "memory"); }
            else              { asm volatile("cp.async.wait_group 0;" ::: "memory"); }
            __syncthreads();

            uint32_t sW = smb + bi * STAGE_B;
            uint32_t sH = sW + 16384;
            #pragma unroll
            for (int ks = 0; ks < 4; ks++) {
                uint32_t xk = (uint32_t)(ks << 5);
                uint32_t aA = sW + (baseA ^ xk);
                uint32_t ahi0[4], ahi1[4];
                ldmx4(ahi0, aA);
                ldmx4(ahi1, aA + 2048);
                uint32_t aB = sH + (baseB ^ xk);
                uint32_t b0[4], b1r[4];
                ldmx4(b0, aB);
                ldmx4(b1r, aB + 2048);
                mma16816h(c[0][0], ahi0, b0);
                mma16816h(c[1][0], ahi1, b0);
                mma16816h(c[0][1], ahi0, b0 + 2);
                mma16816h(c[1][1], ahi1, b0 + 2);
                mma16816h(c[0][2], ahi0, b1r);
                mma16816h(c[1][2], ahi1, b1r);
                mma16816h(c[0][3], ahi0, b1r + 2);
                mma16816h(c[1][3], ahi1, b1r + 2);
            }
            __syncthreads();

            if (kc + 2 < NKC) cp_issue(mc, kc + 2, bi);
        }

        // epilogue: unscale + bias + exact gelu + group max + center proj
        #pragma unroll
        for (int mf = 0; mf < 2; mf++) {
            int row0 = mc * 128 + m0w + mf * 16 + (lane >> 2);
            int row1 = row0 + 8;
            float bias0 = b2[row0], bias1 = b2[row1];
            #pragma unroll
            for (int g = 0; g < 2; g++) {
                float va = -1e30f, vb = -1e30f;
                #pragma unroll
                for (int q = 0; q < 2; q++) {
                    float* cc = c[mf][2 * g + q];
                    va = fmaxf(va, fmaxf(gelu_exact(fmaf(cc[0], INVW2SCALE, bias0)),
                                         gelu_exact(fmaf(cc[1], INVW2SCALE, bias0))));
                    vb = fmaxf(vb, fmaxf(gelu_exact(fmaf(cc[2], INVW2SCALE, bias1)),
                                         gelu_exact(fmaf(cc[3], INVW2SCALE, bias1))));
                }
                va = fmaxf(va, __shfl_xor_sync(0xffffffffu, va, 1));
                va = fmaxf(va, __shfl_xor_sync(0xffffffffu, va, 2));
                vb = fmaxf(vb, __shfl_xor_sync(0xffffffffu, vb, 1));
                vb = fmaxf(vb, __shfl_xor_sync(0xffffffffu, vb, 2));
                if ((lane & 3) == 0) {
                    int gl = (wid >> 2) * 2 + g;
                    int gg = gbase + gl;
                    float c0_ = cen[gl * 3], c1_ = cen[gl * 3 + 1], c2_ = cen[gl * 3 + 2];
                    out[TOK_OFF + ((size_t)b * GG + gg) * ED + row0] =
                        va + c0_ * Wc[row0] + c1_ * Wc[ED + row0] + c2_ * Wc[2 * ED + row0] + bc[row0];
                    out[TOK_OFF + ((size_t)b * GG + gg) * ED + row1] =
                        vb + c0_ * Wc[row1] + c1_ * Wc[ED + row1] + c2_ * Wc[2 * ED + row1] + bc[row1];
                }
            }
        }
        __syncthreads();
    }
}

extern "C" void kernel_launch(void* const* d_in, const int* in_sizes, int n_in,
                              void* d_out, int out_size) {
    const float* xyz = (const float*)d_in[0];
    const float* W1  = (const float*)d_in[1];
    const float* b1  = (const float*)d_in[2];
    const float* W2  = (const float*)d_in[3];
    const float* b2  = (const float*)d_in[4];
    const float* Wc  = (const float*)d_in[5];
    const float* bc  = (const float*)d_in[6];
    float* out = (float*)d_out;

    cudaFuncSetAttribute(k_gemm, cudaFuncAttributeMaxDynamicSharedMemorySize, SM_TOTAL);

    k_minmax<<<BB, 256>>>(xyz);
    k_sort_p1<<<BB * (NN / SCH), 1024>>>(xyz);
    k_sort_gpass<<<BB * NN / 2 / 256, 256>>>(8192, 4096);
    k_sort_p2<<<BB * (NN / SCH), 1024>>>(8192, 0, out, out_size);
    k_sort_gpass<<<BB * NN / 2 / 256, 256>>>(16384, 8192);
    k_sort_gpass<<<BB * NN / 2 / 256, 256>>>(16384, 4096);
    k_sort_p2<<<BB * (NN / SCH), 1024>>>(16384, 1, out, out_size);

    k_prep<<<(HID * ED + 255) / 256, 256>>>(W2);
    k_hid<<<2048, NTH>>>(xyz, W1, b1);
    k_gemm<<<2048, NTH, SM_TOTAL>>>(xyz, b2, Wc, bc, out, out_size);
}

// round 16
// speedup vs baseline: 4.3936x; 1.0363x over previous
#include <cuda_runtime.h>
#include <cuda_bf16.h>
#include <cuda_fp16.h>
#include <cstdint>

#define BB   16
#define NN   16384
#define GS   16
#define GG   1024
#define HID  768
#define ED   384

// output layout (floats): tokens | centers | group_idx(as float)
#define TOK_OFF 0
#define CEN_OFF (BB*GG*ED)
#define IDX_OFF (CEN_OFF + BB*GG*3)
#define TOT_SZ  (IDX_OFF + BB*GG*GS)

// GEMM tiling
#define NPT 256                  // points per CTA (16 groups)
#define KCH 64                   // K chunk
#define NKC (HID/KCH)            // 12
#define TILE_B 16384             // one 128x64 fp16 tile
#define NTH 512                  // threads per CTA (16 warps)
#define W2SCALE 256.0f
#define INVW2SCALE (1.0f/256.0f)

// smem: per stage W2(16K) | H0(16K) | H1(16K); two stages
#define STAGE_B 49152
#define SM_REL    98304                   // 768 floats
#define SM_CEN    101376                  // 48 floats
#define SM_TOTAL  101632

// sort chunking
#define SCH 4096

__device__ float g_mm[BB * 6];
__device__ int   g_sidx[BB * NN];
__device__ unsigned long long g_keys[BB * NN];
__device__ __align__(16) char g_w2hi[3 * NKC * TILE_B];
__device__ __align__(16) char g_h[(size_t)2048 * NKC * TILE_B];   // 402 MB H tiles

__device__ __forceinline__ float gelu_exact(float x) {
    return 0.5f * x * (1.0f + erff(x * 0.70710678118654752f));
}
// tanh-form GELU with HW tanh.approx (only for H, fp16-quantized after)
__device__ __forceinline__ float gelu_fast(float x) {
    float inner = 0.7978845608028654f * fmaf(0.044715f * x, x * x, x);
    float t;
    asm("tanh.approx.f32 %0, %1;" : "=f"(t) : "f"(inner));
    return 0.5f * x * (1.0f + t);
}
__device__ __forceinline__ int part1by2_10(int v) {
    v &= 1023;
    v = (v | (v << 16)) & 50331903;
    v = (v | (v << 8))  & 50393103;
    v = (v | (v << 4))  & 51130563;
    v = (v | (v << 2))  & 153391689;
    return v;
}
__device__ __forceinline__ uint32_t smem_u32(const void* p) {
    uint32_t a;
    asm("{ .reg .u64 t; cvta.to.shared.u64 t, %1; cvt.u32.u64 %0, t; }" : "=r"(a) : "l"(p));
    return a;
}
__device__ __forceinline__ void ldmx4(uint32_t* r, uint32_t a) {
    asm volatile("ldmatrix.sync.aligned.m8n8.x4.shared.b16 {%0,%1,%2,%3}, [%4];"
        : "=r"(r[0]), "=r"(r[1]), "=r"(r[2]), "=r"(r[3]) : "r"(a));
}
__device__ __forceinline__ void mma16816h(float* c, const uint32_t* a, const uint32_t* b) {
    asm volatile(
        "mma.sync.aligned.m16n8k16.row.col.f32.f16.f16.f32 "
        "{%0,%1,%2,%3}, {%4,%5,%6,%7}, {%8,%9}, {%0,%1,%2,%3};"
        : "+f"(c[0]), "+f"(c[1]), "+f"(c[2]), "+f"(c[3])
        : "r"(a[0]), "r"(a[1]), "r"(a[2]), "r"(a[3]), "r"(b[0]), "r"(b[1]));
}
__device__ __forceinline__ uint32_t pack_h2(__half a, __half b) {
    __half2 h2 = __halves2half2(a, b);
    return *(uint32_t*)&h2;
}

// ---------------- Kernel A: per-batch min/max (FROZEN) ----------------
__global__ void k_minmax(const float* __restrict__ xyz) {
    int b = blockIdx.x;
    int t = threadIdx.x;
    const float* p = xyz + (size_t)b * NN * 3;
    float mn0 = 1e30f, mn1 = 1e30f, mn2 = 1e30f;
    float mx0 = -1e30f, mx1 = -1e30f, mx2 = -1e30f;
    for (int i = t; i < NN; i += blockDim.x) {
        float v0 = p[i * 3], v1 = p[i * 3 + 1], v2 = p[i * 3 + 2];
        mn0 = fminf(mn0, v0); mx0 = fmaxf(mx0, v0);
        mn1 = fminf(mn1, v1); mx1 = fmaxf(mx1, v1);
        mn2 = fminf(mn2, v2); mx2 = fmaxf(mx2, v2);
    }
    __shared__ float s[6][256];
    s[0][t] = mn0; s[1][t] = mn1; s[2][t] = mn2;
    s[3][t] = mx0; s[4][t] = mx1; s[5][t] = mx2;
    __syncthreads();
    for (int w = 128; w > 0; w >>= 1) {
        if (t < w) {
            #pragma unroll
            for (int c = 0; c < 3; c++) {
                s[c][t]     = fminf(s[c][t],     s[c][t + w]);
                s[c + 3][t] = fmaxf(s[c + 3][t], s[c + 3][t + w]);
            }
        }
        __syncthreads();
    }
    if (t < 6) g_mm[b * 6 + t] = s[t][0];
}

// ---------------- Sort phase 1: codes + bitonic k=2..4096 (FROZEN network) ----------------
__global__ void __launch_bounds__(1024) k_sort_p1(const float* __restrict__ xyz) {
    __shared__ unsigned long long keys[SCH];
    int blk = blockIdx.x;
    int b = blk >> 2, cidx = blk & 3;
    int base = cidx * SCH;
    int t = threadIdx.x;

    float mn0 = g_mm[b * 6 + 0], mn1 = g_mm[b * 6 + 1], mn2 = g_mm[b * 6 + 2];
    float s0 = fmaxf(__fsub_rn(g_mm[b * 6 + 3], mn0), 1e-6f);
    float s1 = fmaxf(__fsub_rn(g_mm[b * 6 + 4], mn1), 1e-6f);
    float s2 = fmaxf(__fsub_rn(g_mm[b * 6 + 5], mn2), 1e-6f);
    float r0 = __fdiv_rn(1.0f, s0);
    float r1 = __fdiv_rn(1.0f, s1);
    float r2 = __fdiv_rn(1.0f, s2);
    const float* p = xyz + (size_t)b * NN * 3;

    for (int li = t; li < SCH; li += 1024) {
        int i = base + li;
        float u0 = __fmul_rn(__fsub_rn(p[i * 3],     mn0), r0);
        float u1 = __fmul_rn(__fsub_rn(p[i * 3 + 1], mn1), r1);
        float u2 = __fmul_rn(__fsub_rn(p[i * 3 + 2], mn2), r2);
        int q0 = min(max(__float2int_rn(__fmul_rn(u0, 1023.0f)), 0), 1023);
        int q1 = min(max(__float2int_rn(__fmul_rn(u1, 1023.0f)), 0), 1023);
        int q2 = min(max(__float2int_rn(__fmul_rn(u2, 1023.0f)), 0), 1023);
        int code = part1by2_10(q0) | (part1by2_10(q1) << 1) | (part1by2_10(q2) << 2);
        keys[li] = ((unsigned long long)(unsigned)code << 14) | (unsigned long long)i;
    }
    __syncthreads();

    for (int k = 2; k <= SCH; k <<= 1) {
        for (int j = k >> 1; j > 0; j >>= 1) {
            for (int li = t; li < SCH; li += 1024) {
                int lixj = li ^ j;
                if (lixj > li) {
                    unsigned long long a = keys[li], c = keys[lixj];
                    bool up = (((base + li) & k) == 0);
                    if ((a > c) == up) { keys[li] = c; keys[lixj] = a; }
                }
            }
            __syncthreads();
        }
    }

    for (int li = t; li < SCH; li += 1024)
        g_keys[b * NN + base + li] = keys[li];
}

__global__ void k_sort_gpass(int k, int j) {
    int pidx = blockIdx.x * 256 + threadIdx.x;
    int b = pidx >> 13, pin = pidx & 8191;
    int i = ((pin & ~(j - 1)) << 1) | (pin & (j - 1));
    int ixj = i | j;
    unsigned long long* kb = g_keys + (size_t)b * NN;
    unsigned long long a = kb[i], c = kb[ixj];
    bool up = ((i & k) == 0);
    if ((a > c) == up) { kb[i] = c; kb[ixj] = a; }
}

__global__ void __launch_bounds__(1024) k_sort_p2(int k, int final_lvl,
                                                  float* __restrict__ out, int out_size) {
    __shared__ unsigned long long keys[SCH];
    int blk = blockIdx.x;
    int b = blk >> 2, cidx = blk & 3;
    int base = cidx * SCH;
    int t = threadIdx.x;

    for (int li = t; li < SCH; li += 1024) keys[li] = g_keys[b * NN + base + li];
    __syncthreads();

    for (int j = 2048; j > 0; j >>= 1) {
        for (int li = t; li < SCH; li += 1024) {
            int lixj = li ^ j;
            if (lixj > li) {
                unsigned long long a = keys[li], c = keys[lixj];
                bool up = (((base + li) & k) == 0);
                if ((a > c) == up) { keys[li] = c; keys[lixj] = a; }
            }
        }
        __syncthreads();
    }

    if (final_lvl) {
        for (int li = t; li < SCH; li += 1024) {
            int i = base + li;
            int si = (int)(keys[li] & 16383ULL);
            g_sidx[b * NN + i] = si;
            if (out_size >= TOT_SZ) out[IDX_OFF + b * NN + i] = (float)si;
        }
    } else {
        for (int li = t; li < SCH; li += 1024)
            g_keys[b * NN + base + li] = keys[li];
    }
}

// ---------------- Kernel P: 256*W2 -> single fp16 transposed + swizzled tiles ----------------
__global__ void k_prep(const float* __restrict__ W2) {
    int idx = blockIdx.x * 256 + threadIdx.x;
    if (idx >= HID * ED) return;
    int k = idx / ED, n = idx - k * ED;
    __half hi = __float2half(W2[idx] * W2SCALE);
    int mc = n >> 7, row = n & 127, kc = k >> 6, col = k & 63;
    uint32_t off = (uint32_t)(row * 128 + col * 2);
    off ^= (off >> 3) & 0x70;
    size_t tile = (size_t)(mc * NKC + kc) * TILE_B;
    *(__half*)(g_w2hi + tile + off) = hi;
}

// ---------------- Kernel H: layer-1 + fast gelu -> fp16 swizzled tiles ----------------
__global__ void __launch_bounds__(512) k_hid(
    const float* __restrict__ xyz,
    const float* __restrict__ W1, const float* __restrict__ b1)
{
    __shared__ float rel[128 * 3];
    __shared__ float cen[24];
    int t = threadIdx.x;
    int blk = blockIdx.x;                 // 2048 chunks of 128 pts
    int b = blk >> 7;
    int chunk = blk & 127;
    int m0 = chunk * 128;

    if (t < 128) {
        int si = g_sidx[b * NN + m0 + t];
        const float* pp = xyz + ((size_t)b * NN + si) * 3;
        rel[t * 3 + 0] = pp[0];
        rel[t * 3 + 1] = pp[1];
        rel[t * 3 + 2] = pp[2];
    }
    __syncthreads();
    if (t < 24) {
        int g = t / 3, cc = t - g * 3;
        float sum = 0.f;
        #pragma unroll
        for (int p = 0; p < GS; p++) sum += rel[(g * GS + p) * 3 + cc];
        cen[t] = sum * (1.0f / GS);
    }
    __syncthreads();
    for (int i = t; i < 128 * 3; i += 512) rel[i] -= cen[(i / (GS * 3)) * 3 + i % 3];
    __syncthreads();

    int p = t & 127;
    float rx = rel[p * 3], ry = rel[p * 3 + 1], rz = rel[p * 3 + 2];
    int kq = t >> 7;
    uint32_t hswz = (uint32_t)((p & 7) << 4);
    uint32_t hrow = (uint32_t)(p * 128);
    char* gbase = g_h + (size_t)blk * (NKC * TILE_B);

    for (int kc = 0; kc < NKC; kc++) {
        #pragma unroll
        for (int i = 0; i < 2; i++) {
            int k  = kq * 16 + i * 8;
            int kk = kc * KCH + k;
            float4 wa0 = *(const float4*)(W1 + kk);
            float4 wa1 = *(const float4*)(W1 + kk + 4);
            float4 wb0 = *(const float4*)(W1 + HID + kk);
            float4 wb1 = *(const float4*)(W1 + HID + kk + 4);
            float4 wc0 = *(const float4*)(W1 + 2 * HID + kk);
            float4 wc1 = *(const float4*)(W1 + 2 * HID + kk + 4);
            float4 bb0 = *(const float4*)(b1 + kk);
            float4 bb1 = *(const float4*)(b1 + kk + 4);
            float h[8];
            h[0] = gelu_fast(fmaf(rx, wa0.x, fmaf(ry, wb0.x, fmaf(rz, wc0.x, bb0.x))));
            h[1] = gelu_fast(fmaf(rx, wa0.y, fmaf(ry, wb0.y, fmaf(rz, wc0.y, bb0.y))));
            h[2] = gelu_fast(fmaf(rx, wa0.z, fmaf(ry, wb0.z, fmaf(rz, wc0.z, bb0.z))));
            h[3] = gelu_fast(fmaf(rx, wa0.w, fmaf(ry, wb0.w, fmaf(rz, wc0.w, bb0.w))));
            h[4] = gelu_fast(fmaf(rx, wa1.x, fmaf(ry, wb1.x, fmaf(rz, wc1.x, bb1.x))));
            h[5] = gelu_fast(fmaf(rx, wa1.y, fmaf(ry, wb1.y, fmaf(rz, wc1.y, bb1.y))));
            h[6] = gelu_fast(fmaf(rx, wa1.z, fmaf(ry, wb1.z, fmaf(rz, wc1.z, bb1.z))));
            h[7] = gelu_fast(fmaf(rx, wa1.w, fmaf(ry, wb1.w, fmaf(rz, wc1.w, bb1.w))));
            uint32_t hw[4];
            #pragma unroll
            for (int j = 0; j < 4; j++)
                hw[j] = pack_h2(__float2half(h[2 * j]), __float2half(h[2 * j + 1]));
            uint32_t off = hrow + (((uint32_t)(k * 2)) ^ hswz);
            *(uint4*)(gbase + (size_t)kc * TILE_B + off) = make_uint4(hw[0], hw[1], hw[2], hw[3]);
        }
    }
}

// ---------------- Kernel C: fp16 GEMM, 256-pt CTA, warp tile 32x64 ----------------
__global__ void __launch_bounds__(NTH, 1) k_gemm(
    const float* __restrict__ xyz,
    const float* __restrict__ b2,
    const float* __restrict__ Wc, const float* __restrict__ bc,
    float* __restrict__ out, int out_size)
{
    extern __shared__ char sm[];
    uint32_t smb = smem_u32(sm);
    float* rel = (float*)(sm + SM_REL);
    float* cen = (float*)(sm + SM_CEN);

    int t = threadIdx.x, wid = t >> 5, lane = t & 31;
    int blk = blockIdx.x;                 // 1024
    int b = blk >> 6;
    int chunk = blk & 63;                 // 256-pt chunk
    int gbase = chunk * 16;
    int m0 = chunk * NPT;
    // two 128-pt H tile bases
    const char* hg0 = g_h + (size_t)(blk * 2) * (NKC * TILE_B);
    const char* hg1 = hg0 + (size_t)(NKC * TILE_B);

    if (t < NPT) {
        int si = g_sidx[b * NN + m0 + t];
        const float* pp = xyz + ((size_t)b * NN + si) * 3;
        rel[t * 3 + 0] = pp[0];
        rel[t * 3 + 1] = pp[1];
        rel[t * 3 + 2] = pp[2];
    }
    __syncthreads();
    if (t < 48) {
        int g = t / 3, cc = t - g * 3;
        float sum = 0.f;
        #pragma unroll
        for (int p = 0; p < GS; p++) sum += rel[(g * GS + p) * 3 + cc];
        float cv = sum * (1.0f / GS);
        cen[t] = cv;
        if (out_size >= CEN_OFF + BB * GG * 3)
            out[CEN_OFF + ((size_t)b * GG + gbase + g) * 3 + cc] = cv;
    }
    __syncthreads();

    // cp.async stage: W2(mc,kc) | H0(kc) | H1(kc) into stage bi
    auto cp_issue = [&](int mc, int kc, int bi) {
        size_t wt = (size_t)(mc * NKC + kc) * TILE_B;
        const char* sw = g_w2hi + wt;
        const char* h0 = hg0 + (size_t)kc * TILE_B;
        const char* h1 = hg1 + (size_t)kc * TILE_B;
        uint32_t d = smb + bi * STAGE_B;
        #pragma unroll
        for (int i = 0; i < 2; i++) {
            uint32_t o = (uint32_t)(t * 16 + i * 8192);
            asm volatile("cp.async.cg.shared.global [%0], [%1], 16;"
                :: "r"(d + o), "l"(__cvta_generic_to_global(sw + o)) : "memory");
            asm volatile("cp.async.cg.shared.global [%0], [%1], 16;"
                :: "r"(d + 16384 + o), "l"(__cvta_generic_to_global(h0 + o)) : "memory");
            asm volatile("cp.async.cg.shared.global [%0], [%1], 16;"
                :: "r"(d + 32768 + o), "l"(__cvta_generic_to_global(h1 + o)) : "memory");
        }
        asm volatile("cp.async.commit_group;" ::: "memory");
    };

    int m0w = (wid & 3) * 32;        // warp M offset (cols within 128)
    int q   = wid >> 2;              // point quadrant: 64 pts each
    int tileSel = q >> 1;            // 0: pts 0-127, 1: pts 128-255

    int rowA = m0w + (lane & 15);
    uint32_t baseA = (uint32_t)(rowA * 128) + ((((uint32_t)(lane >> 4)) << 4) ^ ((uint32_t)(rowA & 7) << 4));
    int gq = lane >> 3;
    int rowB = (q & 1) * 64 + (gq >> 1) * 8 + (lane & 7);   // row within 128-pt tile
    uint32_t baseB = (uint32_t)(rowB * 128) + ((((uint32_t)(gq & 1)) << 4) ^ ((uint32_t)(rowB & 7) << 4));
    uint32_t hTileOff = 16384u + (uint32_t)tileSel * 16384u;

    for (int mc = 0; mc < 3; mc++) {
        float c[2][8][4];
        #pragma unroll
        for (int mf = 0; mf < 2; mf++)
            #pragma unroll
            for (int nf = 0; nf < 8; nf++)
                #pragma unroll
                for (int qq = 0; qq < 4; qq++) c[mf][nf][qq] = 0.f;

        cp_issue(mc, 0, 0);
        cp_issue(mc, 1, 1);

        for (int kc = 0; kc < NKC; kc++) {
            int bi = kc & 1;
            if (kc < NKC - 1) { asm volatile("cp.async.wait_group 1;" ::: "memory"); }
            else              { asm volatile("cp.async.wait_group 0;" ::: "memory"); }
            __syncthreads();

            uint32_t sW = smb + bi * STAGE_B;
            uint32_t sH = sW + hTileOff;
            #pragma unroll
            for (int ks = 0; ks < 4; ks++) {
                uint32_t xk = (uint32_t)(ks << 5);
                uint32_t aA = sW + (baseA ^ xk);
                uint32_t a0[4], a1[4];
                ldmx4(a0, aA);
                ldmx4(a1, aA + 2048);
                uint32_t aB = sH + (baseB ^ xk);
                #pragma unroll
                for (int nfp = 0; nfp < 4; nfp++) {
                    uint32_t bf[4];
                    ldmx4(bf, aB + (uint32_t)nfp * 2048u);
                    mma16816h(c[0][2 * nfp],     a0, bf);
                    mma16816h(c[1][2 * nfp],     a1, bf);
                    mma16816h(c[0][2 * nfp + 1], a0, bf + 2);
                    mma16816h(c[1][2 * nfp + 1], a1, bf + 2);
                }
            }
            __syncthreads();

            if (kc + 2 < NKC) cp_issue(mc, kc + 2, bi);
        }

        // epilogue: unscale + bias + exact gelu + 16-pt group max + center proj
        #pragma unroll
        for (int mf = 0; mf < 2; mf++) {
            int row0 = mc * 128 + m0w + mf * 16 + (lane >> 2);
            int row1 = row0 + 8;
            float bias0 = b2[row0], bias1 = b2[row1];
            #pragma unroll
            for (int g = 0; g < 4; g++) {
                float va = -1e30f, vb = -1e30f;
                #pragma unroll
                for (int qq = 0; qq < 2; qq++) {
                    float* cc = c[mf][2 * g + qq];
                    va = fmaxf(va, fmaxf(gelu_exact(fmaf(cc[0], INVW2SCALE, bias0)),
                                         gelu_exact(fmaf(cc[1], INVW2SCALE, bias0))));
                    vb = fmaxf(vb, fmaxf(gelu_exact(fmaf(cc[2], INVW2SCALE, bias1)),
                                         gelu_exact(fmaf(cc[3], INVW2SCALE, bias1))));
                }
                va = fmaxf(va, __shfl_xor_sync(0xffffffffu, va, 1));
                va = fmaxf(va, __shfl_xor_sync(0xffffffffu, va, 2));
                vb = fmaxf(vb, __shfl_xor_sync(0xffffffffu, vb, 1));
                vb = fmaxf(vb, __shfl_xor_sync(0xffffffffu, vb, 2));
                if ((lane & 3) == 0) {
                    int gl = q * 4 + g;               // 16 groups per CTA
                    int gg = gbase + gl;
                    float c0_ = cen[gl * 3], c1_ = cen[gl * 3 + 1], c2_ = cen[gl * 3 + 2];
                    out[TOK_OFF + ((size_t)b * GG + gg) * ED + row0] =
                        va + c0_ * Wc[row0] + c1_ * Wc[ED + row0] + c2_ * Wc[2 * ED + row0] + bc[row0];
                    out[TOK_OFF + ((size_t)b * GG + gg) * ED + row1] =
                        vb + c0_ * Wc[row1] + c1_ * Wc[ED + row1] + c2_ * Wc[2 * ED + row1] + bc[row1];
                }
            }
        }
        __syncthreads();
    }
}

extern "C" void kernel_launch(void* const* d_in, const int* in_sizes, int n_in,
                              void* d_out, int out_size) {
    const float* xyz = (const float*)d_in[0];
    const float* W1  = (const float*)d_in[1];
    const float* b1  = (const float*)d_in[2];
    const float* W2  = (const float*)d_in[3];
    const float* b2  = (const float*)d_in[4];
    const float* Wc  = (const float*)d_in[5];
    const float* bc  = (const float*)d_in[6];
    float* out = (float*)d_out;

    cudaFuncSetAttribute(k_gemm, cudaFuncAttributeMaxDynamicSharedMemorySize, SM_TOTAL);

    k_minmax<<<BB, 256>>>(xyz);
    k_sort_p1<<<BB * (NN / SCH), 1024>>>(xyz);
    k_sort_gpass<<<BB * NN / 2 / 256, 256>>>(8192, 4096);
    k_sort_p2<<<BB * (NN / SCH), 1024>>>(8192, 0, out, out_size);
    k_sort_gpass<<<BB * NN / 2 / 256, 256>>>(16384, 8192);
    k_sort_gpass<<<BB * NN / 2 / 256, 256>>>(16384, 4096);
    k_sort_p2<<<BB * (NN / SCH), 1024>>>(16384, 1, out, out_size);

    k_prep<<<(HID * ED + 255) / 256, 256>>>(W2);
    k_hid<<<2048, 512>>>(xyz, W1, b1);
    k_gemm<<<BB * NN / NPT, NTH, SM_TOTAL>>>(xyz, b2, Wc, bc, out, out_size);
}

// round 17
// speedup vs baseline: 4.7928x; 1.0908x over previous
#include <cuda_runtime.h>
#include <cuda_bf16.h>
#include <cuda_fp16.h>
#include <cstdint>

#define BB   16
#define NN   16384
#define GS   16
#define GG   1024
#define HID  768
#define ED   384

// output layout (floats): tokens | centers | group_idx(as float)
#define TOK_OFF 0
#define CEN_OFF (BB*GG*ED)
#define IDX_OFF (CEN_OFF + BB*GG*3)
#define TOT_SZ  (IDX_OFF + BB*GG*GS)

// GEMM tiling
#define NPT 128                  // points per CTA (8 groups)
#define KCH 64                   // K chunk
#define NKC (HID/KCH)            // 12
#define TILE_B 16384             // one 128x64 fp16 tile
#define NTH 256                  // threads per CTA (8 warps), 2 CTAs/SM
#define W2SCALE 256.0f
#define INVW2SCALE (1.0f/256.0f)

// smem: per stage W2(16K) | H(16K); two stages
#define STAGE_B 32768
#define SM_REL    65536                   // 384 floats
#define SM_CEN    67072                   // 24 floats
#define SM_TOTAL  67200

// sort chunking
#define SCH 4096

__device__ float g_mm[BB * 6];
__device__ int   g_sidx[BB * NN];
__device__ unsigned long long g_keys[BB * NN];
__device__ __align__(16) char g_w2hi[3 * NKC * TILE_B];
__device__ __align__(16) char g_h[(size_t)2048 * NKC * TILE_B];   // 402 MB H tiles

__device__ __forceinline__ float gelu_exact(float x) {
    return 0.5f * x * (1.0f + erff(x * 0.70710678118654752f));
}
// tanh-form GELU with HW tanh.approx (only for H, fp16-quantized after)
__device__ __forceinline__ float gelu_fast(float x) {
    float inner = 0.7978845608028654f * fmaf(0.044715f * x, x * x, x);
    float t;
    asm("tanh.approx.f32 %0, %1;" : "=f"(t) : "f"(inner));
    return 0.5f * x * (1.0f + t);
}
__device__ __forceinline__ int part1by2_10(int v) {
    v &= 1023;
    v = (v | (v << 16)) & 50331903;
    v = (v | (v << 8))  & 50393103;
    v = (v | (v << 4))  & 51130563;
    v = (v | (v << 2))  & 153391689;
    return v;
}
__device__ __forceinline__ uint32_t smem_u32(const void* p) {
    uint32_t a;
    asm("{ .reg .u64 t; cvta.to.shared.u64 t, %1; cvt.u32.u64 %0, t; }" : "=r"(a) : "l"(p));
    return a;
}
__device__ __forceinline__ void ldmx4(uint32_t* r, uint32_t a) {
    asm volatile("ldmatrix.sync.aligned.m8n8.x4.shared.b16 {%0,%1,%2,%3}, [%4];"
        : "=r"(r[0]), "=r"(r[1]), "=r"(r[2]), "=r"(r[3]) : "r"(a));
}
__device__ __forceinline__ void mma16816h(float* c, const uint32_t* a, const uint32_t* b) {
    asm volatile(
        "mma.sync.aligned.m16n8k16.row.col.f32.f16.f16.f32 "
        "{%0,%1,%2,%3}, {%4,%5,%6,%7}, {%8,%9}, {%0,%1,%2,%3};"
        : "+f"(c[0]), "+f"(c[1]), "+f"(c[2]), "+f"(c[3])
        : "r"(a[0]), "r"(a[1]), "r"(a[2]), "r"(a[3]), "r"(b[0]), "r"(b[1]));
}
__device__ __forceinline__ uint32_t pack_h2(__half a, __half b) {
    __half2 h2 = __halves2half2(a, b);
    return *(uint32_t*)&h2;
}

// ---------------- Kernel A: per-batch min/max (FROZEN) ----------------
__global__ void k_minmax(const float* __restrict__ xyz) {
    int b = blockIdx.x;
    int t = threadIdx.x;
    const float* p = xyz + (size_t)b * NN * 3;
    float mn0 = 1e30f, mn1 = 1e30f, mn2 = 1e30f;
    float mx0 = -1e30f, mx1 = -1e30f, mx2 = -1e30f;
    for (int i = t; i < NN; i += blockDim.x) {
        float v0 = p[i * 3], v1 = p[i * 3 + 1], v2 = p[i * 3 + 2];
        mn0 = fminf(mn0, v0); mx0 = fmaxf(mx0, v0);
        mn1 = fminf(mn1, v1); mx1 = fmaxf(mx1, v1);
        mn2 = fminf(mn2, v2); mx2 = fmaxf(mx2, v2);
    }
    __shared__ float s[6][256];
    s[0][t] = mn0; s[1][t] = mn1; s[2][t] = mn2;
    s[3][t] = mx0; s[4][t] = mx1; s[5][t] = mx2;
    __syncthreads();
    for (int w = 128; w > 0; w >>= 1) {
        if (t < w) {
            #pragma unroll
            for (int c = 0; c < 3; c++) {
                s[c][t]     = fminf(s[c][t],     s[c][t + w]);
                s[c + 3][t] = fmaxf(s[c + 3][t], s[c + 3][t + w]);
            }
        }
        __syncthreads();
    }
    if (t < 6) g_mm[b * 6 + t] = s[t][0];
}

// ---------------- Sort phase 1: codes + bitonic k=2..4096 (FROZEN network) ----------------
__global__ void __launch_bounds__(1024) k_sort_p1(const float* __restrict__ xyz) {
    __shared__ unsigned long long keys[SCH];
    int blk = blockIdx.x;
    int b = blk >> 2, cidx = blk & 3;
    int base = cidx * SCH;
    int t = threadIdx.x;

    float mn0 = g_mm[b * 6 + 0], mn1 = g_mm[b * 6 + 1], mn2 = g_mm[b * 6 + 2];
    float s0 = fmaxf(__fsub_rn(g_mm[b * 6 + 3], mn0), 1e-6f);
    float s1 = fmaxf(__fsub_rn(g_mm[b * 6 + 4], mn1), 1e-6f);
    float s2 = fmaxf(__fsub_rn(g_mm[b * 6 + 5], mn2), 1e-6f);
    float r0 = __fdiv_rn(1.0f, s0);
    float r1 = __fdiv_rn(1.0f, s1);
    float r2 = __fdiv_rn(1.0f, s2);
    const float* p = xyz + (size_t)b * NN * 3;

    for (int li = t; li < SCH; li += 1024) {
        int i = base + li;
        float u0 = __fmul_rn(__fsub_rn(p[i * 3],     mn0), r0);
        float u1 = __fmul_rn(__fsub_rn(p[i * 3 + 1], mn1), r1);
        float u2 = __fmul_rn(__fsub_rn(p[i * 3 + 2], mn2), r2);
        int q0 = min(max(__float2int_rn(__fmul_rn(u0, 1023.0f)), 0), 1023);
        int q1 = min(max(__float2int_rn(__fmul_rn(u1, 1023.0f)), 0), 1023);
        int q2 = min(max(__float2int_rn(__fmul_rn(u2, 1023.0f)), 0), 1023);
        int code = part1by2_10(q0) | (part1by2_10(q1) << 1) | (part1by2_10(q2) << 2);
        keys[li] = ((unsigned long long)(unsigned)code << 14) | (unsigned long long)i;
    }
    __syncthreads();

    for (int k = 2; k <= SCH; k <<= 1) {
        for (int j = k >> 1; j > 0; j >>= 1) {
            for (int li = t; li < SCH; li += 1024) {
                int lixj = li ^ j;
                if (lixj > li) {
                    unsigned long long a = keys[li], c = keys[lixj];
                    bool up = (((base + li) & k) == 0);
                    if ((a > c) == up) { keys[li] = c; keys[lixj] = a; }
                }
            }
            __syncthreads();
        }
    }

    for (int li = t; li < SCH; li += 1024)
        g_keys[b * NN + base + li] = keys[li];
}

__global__ void k_sort_gpass(int k, int j) {
    int pidx = blockIdx.x * 256 + threadIdx.x;
    int b = pidx >> 13, pin = pidx & 8191;
    int i = ((pin & ~(j - 1)) << 1) | (pin & (j - 1));
    int ixj = i | j;
    unsigned long long* kb = g_keys + (size_t)b * NN;
    unsigned long long a = kb[i], c = kb[ixj];
    bool up = ((i & k) == 0);
    if ((a > c) == up) { kb[i] = c; kb[ixj] = a; }
}

__global__ void __launch_bounds__(1024) k_sort_p2(int k, int final_lvl,
                                                  float* __restrict__ out, int out_size) {
    __shared__ unsigned long long keys[SCH];
    int blk = blockIdx.x;
    int b = blk >> 2, cidx = blk & 3;
    int base = cidx * SCH;
    int t = threadIdx.x;

    for (int li = t; li < SCH; li += 1024) keys[li] = g_keys[b * NN + base + li];
    __syncthreads();

    for (int j = 2048; j > 0; j >>= 1) {
        for (int li = t; li < SCH; li += 1024) {
            int lixj = li ^ j;
            if (lixj > li) {
                unsigned long long a = keys[li], c = keys[lixj];
                bool up = (((base + li) & k) == 0);
                if ((a > c) == up) { keys[li] = c; keys[lixj] = a; }
            }
        }
        __syncthreads();
    }

    if (final_lvl) {
        for (int li = t; li < SCH; li += 1024) {
            int i = base + li;
            int si = (int)(keys[li] & 16383ULL);
            g_sidx[b * NN + i] = si;
            if (out_size >= TOT_SZ) out[IDX_OFF + b * NN + i] = (float)si;
        }
    } else {
        for (int li = t; li < SCH; li += 1024)
            g_keys[b * NN + base + li] = keys[li];
    }
}

// ---------------- Kernel P: 256*W2 -> single fp16 transposed + swizzled tiles ----------------
__global__ void k_prep(const float* __restrict__ W2) {
    int idx = blockIdx.x * 256 + threadIdx.x;
    if (idx >= HID * ED) return;
    int k = idx / ED, n = idx - k * ED;
    __half hi = __float2half(W2[idx] * W2SCALE);
    int mc = n >> 7, row = n & 127, kc = k >> 6, col = k & 63;
    uint32_t off = (uint32_t)(row * 128 + col * 2);
    off ^= (off >> 3) & 0x70;
    size_t tile = (size_t)(mc * NKC + kc) * TILE_B;
    *(__half*)(g_w2hi + tile + off) = hi;
}

// ---------------- Kernel H: layer-1 + fast gelu -> fp16 swizzled tiles ----------------
__global__ void __launch_bounds__(512) k_hid(
    const float* __restrict__ xyz,
    const float* __restrict__ W1, const float* __restrict__ b1)
{
    __shared__ float rel[128 * 3];
    __shared__ float cen[24];
    int t = threadIdx.x;
    int blk = blockIdx.x;                 // 2048 chunks of 128 pts
    int b = blk >> 7;
    int chunk = blk & 127;
    int m0 = chunk * 128;

    if (t < 128) {
        int si = g_sidx[b * NN + m0 + t];
        const float* pp = xyz + ((size_t)b * NN + si) * 3;
        rel[t * 3 + 0] = pp[0];
        rel[t * 3 + 1] = pp[1];
        rel[t * 3 + 2] = pp[2];
    }
    __syncthreads();
    if (t < 24) {
        int g = t / 3, cc = t - g * 3;
        float sum = 0.f;
        #pragma unroll
        for (int p = 0; p < GS; p++) sum += rel[(g * GS + p) * 3 + cc];
        cen[t] = sum * (1.0f / GS);
    }
    __syncthreads();
    for (int i = t; i < 128 * 3; i += 512) rel[i] -= cen[(i / (GS * 3)) * 3 + i % 3];
    __syncthreads();

    int p = t & 127;
    float rx = rel[p * 3], ry = rel[p * 3 + 1], rz = rel[p * 3 + 2];
    int kq = t >> 7;
    uint32_t hswz = (uint32_t)((p & 7) << 4);
    uint32_t hrow = (uint32_t)(p * 128);
    char* gbase = g_h + (size_t)blk * (NKC * TILE_B);

    for (int kc = 0; kc < NKC; kc++) {
        #pragma unroll
        for (int i = 0; i < 2; i++) {
            int k  = kq * 16 + i * 8;
            int kk = kc * KCH + k;
            float4 wa0 = *(const float4*)(W1 + kk);
            float4 wa1 = *(const float4*)(W1 + kk + 4);
            float4 wb0 = *(const float4*)(W1 + HID + kk);
            float4 wb1 = *(const float4*)(W1 + HID + kk + 4);
            float4 wc0 = *(const float4*)(W1 + 2 * HID + kk);
            float4 wc1 = *(const float4*)(W1 + 2 * HID + kk + 4);
            float4 bb0 = *(const float4*)(b1 + kk);
            float4 bb1 = *(const float4*)(b1 + kk + 4);
            float h[8];
            h[0] = gelu_fast(fmaf(rx, wa0.x, fmaf(ry, wb0.x, fmaf(rz, wc0.x, bb0.x))));
            h[1] = gelu_fast(fmaf(rx, wa0.y, fmaf(ry, wb0.y, fmaf(rz, wc0.y, bb0.y))));
            h[2] = gelu_fast(fmaf(rx, wa0.z, fmaf(ry, wb0.z, fmaf(rz, wc0.z, bb0.z))));
            h[3] = gelu_fast(fmaf(rx, wa0.w, fmaf(ry, wb0.w, fmaf(rz, wc0.w, bb0.w))));
            h[4] = gelu_fast(fmaf(rx, wa1.x, fmaf(ry, wb1.x, fmaf(rz, wc1.x, bb1.x))));
            h[5] = gelu_fast(fmaf(rx, wa1.y, fmaf(ry, wb1.y, fmaf(rz, wc1.y, bb1.y))));
            h[6] = gelu_fast(fmaf(rx, wa1.z, fmaf(ry, wb1.z, fmaf(rz, wc1.z, bb1.z))));
            h[7] = gelu_fast(fmaf(rx, wa1.w, fmaf(ry, wb1.w, fmaf(rz, wc1.w, bb1.w))));
            uint32_t hw[4];
            #pragma unroll
            for (int j = 0; j < 4; j++)
                hw[j] = pack_h2(__float2half(h[2 * j]), __float2half(h[2 * j + 1]));
            uint32_t off = hrow + (((uint32_t)(k * 2)) ^ hswz);
            *(uint4*)(gbase + (size_t)kc * TILE_B + off) = make_uint4(hw[0], hw[1], hw[2], hw[3]);
        }
    }
}

// ---------------- Kernel C: fp16 GEMM, 128-pt CTA, 8 warps (32x64 tile), 2 CTAs/SM ----------------
__global__ void __launch_bounds__(NTH, 2) k_gemm(
    const float* __restrict__ xyz,
    const float* __restrict__ b2,
    const float* __restrict__ Wc, const float* __restrict__ bc,
    float* __restrict__ out, int out_size)
{
    extern __shared__ char sm[];
    uint32_t smb = smem_u32(sm);
    float* rel = (float*)(sm + SM_REL);
    float* cen = (float*)(sm + SM_CEN);

    int t = threadIdx.x, wid = t >> 5, lane = t & 31;
    int blk = blockIdx.x;                 // 2048
    int b = blk >> 7;
    int chunk = blk & 127;
    int gbase = chunk * 8;
    int m0 = chunk * NPT;
    const char* hgbase = g_h + (size_t)blk * (NKC * TILE_B);

    if (t < NPT) {
        int si = g_sidx[b * NN + m0 + t];
        const float* pp = xyz + ((size_t)b * NN + si) * 3;
        rel[t * 3 + 0] = pp[0];
        rel[t * 3 + 1] = pp[1];
        rel[t * 3 + 2] = pp[2];
    }
    __syncthreads();
    if (t < 24) {
        int g = t / 3, cc = t - g * 3;
        float sum = 0.f;
        #pragma unroll
        for (int p = 0; p < GS; p++) sum += rel[(g * GS + p) * 3 + cc];
        float cv = sum * (1.0f / GS);
        cen[t] = cv;
        if (out_size >= CEN_OFF + BB * GG * 3)
            out[CEN_OFF + ((size_t)b * GG + gbase + g) * 3 + cc] = cv;
    }
    __syncthreads();

    // cp.async stage: W2(mc,kc) | H(kc) into stage bi
    auto cp_issue = [&](int mc, int kc, int bi) {
        size_t wt = (size_t)(mc * NKC + kc) * TILE_B;
        const char* sw = g_w2hi + wt;
        const char* hh = hgbase + (size_t)kc * TILE_B;
        uint32_t d = smb + bi * STAGE_B;
        #pragma unroll
        for (int i = 0; i < 4; i++) {
            uint32_t o = (uint32_t)(t * 16 + i * 4096);
            asm volatile("cp.async.cg.shared.global [%0], [%1], 16;"
                :: "r"(d + o), "l"(__cvta_generic_to_global(sw + o)) : "memory");
            asm volatile("cp.async.cg.shared.global [%0], [%1], 16;"
                :: "r"(d + 16384 + o), "l"(__cvta_generic_to_global(hh + o)) : "memory");
        }
        asm volatile("cp.async.commit_group;" ::: "memory");
    };

    int m0w = (wid & 3) * 32;        // warp M offset (cols within 128)
    int q   = wid >> 2;              // point half (64 pts each)

    int rowA = m0w + (lane & 15);
    uint32_t baseA = (uint32_t)(rowA * 128) + ((((uint32_t)(lane >> 4)) << 4) ^ ((uint32_t)(rowA & 7) << 4));
    int gq = lane >> 3;
    int rowB = q * 64 + (gq >> 1) * 8 + (lane & 7);
    uint32_t baseB = (uint32_t)(rowB * 128) + ((((uint32_t)(gq & 1)) << 4) ^ ((uint32_t)(rowB & 7) << 4));

    for (int mc = 0; mc < 3; mc++) {
        float c[2][8][4];
        #pragma unroll
        for (int mf = 0; mf < 2; mf++)
            #pragma unroll
            for (int nf = 0; nf < 8; nf++)
                #pragma unroll
                for (int qq = 0; qq < 4; qq++) c[mf][nf][qq] = 0.f;

        cp_issue(mc, 0, 0);
        cp_issue(mc, 1, 1);

        for (int kc = 0; kc < NKC; kc++) {
            int bi = kc & 1;
            if (kc < NKC - 1) { asm volatile("cp.async.wait_group 1;" ::: "memory"); }
            else              { asm volatile("cp.async.wait_group 0;" ::: "memory"); }
            __syncthreads();

            uint32_t sW = smb + bi * STAGE_B;
            uint32_t sH = sW + 16384;
            #pragma unroll
            for (int ks = 0; ks < 4; ks++) {
                uint32_t xk = (uint32_t)(ks << 5);
                uint32_t aA = sW + (baseA ^ xk);
                uint32_t a0[4], a1[4];
                ldmx4(a0, aA);
                ldmx4(a1, aA + 2048);
                uint32_t aB = sH + (baseB ^ xk);
                #pragma unroll
                for (int nfp = 0; nfp < 4; nfp++) {
                    uint32_t bf[4];
                    ldmx4(bf, aB + (uint32_t)nfp * 2048u);
                    mma16816h(c[0][2 * nfp],     a0, bf);
                    mma16816h(c[1][2 * nfp],     a1, bf);
                    mma16816h(c[0][2 * nfp + 1], a0, bf + 2);
                    mma16816h(c[1][2 * nfp + 1], a1, bf + 2);
                }
            }
            __syncthreads();

            if (kc + 2 < NKC) cp_issue(mc, kc + 2, bi);
        }

        // epilogue: unscale + bias + exact gelu + 16-pt group max + center proj
        #pragma unroll
        for (int mf = 0; mf < 2; mf++) {
            int row0 = mc * 128 + m0w + mf * 16 + (lane >> 2);
            int row1 = row0 + 8;
            float bias0 = b2[row0], bias1 = b2[row1];
            #pragma unroll
            for (int g = 0; g < 4; g++) {
                float va = -1e30f, vb = -1e30f;
                #pragma unroll
                for (int qq = 0; qq < 2; qq++) {
                    float* cc = c[mf][2 * g + qq];
                    va = fmaxf(va, fmaxf(gelu_exact(fmaf(cc[0], INVW2SCALE, bias0)),
                                         gelu_exact(fmaf(cc[1], INVW2SCALE, bias0))));
                    vb = fmaxf(vb, fmaxf(gelu_exact(fmaf(cc[2], INVW2SCALE, bias1)),
                                         gelu_exact(fmaf(cc[3], INVW2SCALE, bias1))));
                }
                va = fmaxf(va, __shfl_xor_sync(0xffffffffu, va, 1));
                va = fmaxf(va, __shfl_xor_sync(0xffffffffu, va, 2));
                vb = fmaxf(vb, __shfl_xor_sync(0xffffffffu, vb, 1));
                vb = fmaxf(vb, __shfl_xor_sync(0xffffffffu, vb, 2));
                if ((lane & 3) == 0) {
                    int gl = q * 4 + g;               // 8 groups per CTA
                    int gg = gbase + gl;
                    float c0_ = cen[gl * 3], c1_ = cen[gl * 3 + 1], c2_ = cen[gl * 3 + 2];
                    out[TOK_OFF + ((size_t)b * GG + gg) * ED + row0] =
                        va + c0_ * Wc[row0] + c1_ * Wc[ED + row0] + c2_ * Wc[2 * ED + row0] + bc[row0];
                    out[TOK_OFF + ((size_t)b * GG + gg) * ED + row1] =
                        vb + c0_ * Wc[row1] + c1_ * Wc[ED + row1] + c2_ * Wc[2 * ED + row1] + bc[row1];
                }
            }
        }
        __syncthreads();
    }
}

extern "C" void kernel_launch(void* const* d_in, const int* in_sizes, int n_in,
                              void* d_out, int out_size) {
    const float* xyz = (const float*)d_in[0];
    const float* W1  = (const float*)d_in[1];
    const float* b1  = (const float*)d_in[2];
    const float* W2  = (const float*)d_in[3];
    const float* b2  = (const float*)d_in[4];
    const float* Wc  = (const float*)d_in[5];
    const float* bc  = (const float*)d_in[6];
    float* out = (float*)d_out;

    cudaFuncSetAttribute(k_gemm, cudaFuncAttributeMaxDynamicSharedMemorySize, SM_TOTAL);

    k_minmax<<<BB, 256>>>(xyz);
    k_sort_p1<<<BB * (NN / SCH), 1024>>>(xyz);
    k_sort_gpass<<<BB * NN / 2 / 256, 256>>>(8192, 4096);
    k_sort_p2<<<BB * (NN / SCH), 1024>>>(8192, 0, out, out_size);
    k_sort_gpass<<<BB * NN / 2 / 256, 256>>>(16384, 8192);
    k_sort_gpass<<<BB * NN / 2 / 256, 256>>>(16384, 4096);
    k_sort_p2<<<BB * (NN / SCH), 1024>>>(16384, 1, out, out_size);

    k_prep<<<(HID * ED + 255) / 256, 256>>>(W2);
    k_hid<<<2048, 512>>>(xyz, W1, b1);
    k_gemm<<<BB * NN / NPT, NTH, SM_TOTAL>>>(xyz, b2, Wc, bc, out, out_size);
}